// round 5
// baseline (speedup 1.0000x reference)
#include <cuda_runtime.h>
#include <cstdint>

// ---------------------------------------------------------------------------
// InceptionResNet sparse-conv block, restructured as dense GEMMs + gather-sums
//
//   t = f @ concat_k(W_k)   (dense SGEMM)
//   conv3(f)[i] = sum_k mask[i,k] * t[nbr[i,k], k*Cout : (k+1)*Cout]
//
// All fp32 round 0. Scratch lives in __device__ globals (allocation-free rule).
// ---------------------------------------------------------------------------

#define NPTS 500000

// scratch (driver-allocated at module load; each array < 2^31 bytes)
__device__ float g_t[448000000];      // [N, up to 896] GEMM output scratch (1.79 GB)
__device__ float g_h0 [NPTS * 32];    // relu(x@W00+b00)
__device__ float g_h1 [NPTS * 32];    // relu(conv3(x,W10)+b10)
__device__ float g_h0b[NPTS * 32];    // relu(conv3(h0,W01)+b01)
__device__ float g_p64[NPTS * 64];    // partial accumulator for split conv3(h1,W11)
__device__ float g_W10t[128 * 864];   // W10 transposed to [Cin=128, 27*32]
__device__ float g_W01t[ 32 * 864];   // W01 -> [32, 27*32]
__device__ float g_W11t[ 32 * 1728];  // W11 -> [32, 27*64]

// ---------------------------------------------------------------------------
// Weight re-layout: [K, Cin, Co] -> [Cin, K*Co]
// ---------------------------------------------------------------------------
__global__ void prep_w(const float* __restrict__ W10,
                       const float* __restrict__ W01,
                       const float* __restrict__ W11)
{
    int idx = blockIdx.x * 256 + threadIdx.x;
    if (idx < 27 * 128 * 32) {            // W10: idx = (k*128 + j)*32 + c
        int c = idx & 31, j = (idx >> 5) & 127, k = idx >> 12;
        g_W10t[j * 864 + k * 32 + c] = W10[idx];
    }
    if (idx < 27 * 32 * 32) {             // W01: idx = (k*32 + j)*32 + c
        int c = idx & 31, j = (idx >> 5) & 31, k = idx >> 10;
        g_W01t[j * 864 + k * 32 + c] = W01[idx];
    }
    if (idx < 27 * 32 * 64) {             // W11: idx = (k*32 + j)*64 + c
        int c = idx & 63, j = (idx >> 6) & 31, k = idx >> 11;
        g_W11t[j * 1728 + k * 64 + c] = W11[idx];
    }
}

// ---------------------------------------------------------------------------
// fp32 SGEMM: C[M,Ncol] = A[M,K] @ B[K,Ncol]  (+bias, relu, +residual)
// Tile 128(M) x 64(N), kc=16, 128 threads, 8x8 register blocking per thread.
// Per k-step per thread: 8+8 floats from smem per 64 FMA -> 128 B/cyc at peak.
// ---------------------------------------------------------------------------
template<bool BIAS, bool RELU, bool RES>
__global__ __launch_bounds__(128)
void sgemm_kernel(const float* __restrict__ A, int lda,
                  const float* __restrict__ B, int ldb,
                  float* __restrict__ C, int ldc,
                  int M, int K, int Ncol,
                  const float* __restrict__ bias,
                  const float* __restrict__ res, int ldres)
{
    __shared__ float As[16][128];
    __shared__ float Bs[16][64];

    const int tid = threadIdx.x;
    const int tx  = tid & 7;    // 8 col-groups of 8
    const int ty  = tid >> 3;   // 16 row-groups of 8
    const int m0  = blockIdx.x * 128;
    const int n0  = blockIdx.y * 64;

    float acc[8][8];
#pragma unroll
    for (int i = 0; i < 8; i++)
#pragma unroll
        for (int j = 0; j < 8; j++) acc[i][j] = 0.f;

    for (int k0 = 0; k0 < K; k0 += 16) {
        // Stage A tile (128 rows x 16 k), transposed to As[k][m]
#pragma unroll
        for (int i = 0; i < 4; i++) {
            int v  = tid + i * 128;      // float4 id 0..511
            int r  = v >> 2;             // row 0..127
            int kk = (v & 3) * 4;
            int m  = m0 + r;
            float4 a = make_float4(0.f, 0.f, 0.f, 0.f);
            if (m < M)
                a = *reinterpret_cast<const float4*>(A + (size_t)m * lda + k0 + kk);
            As[kk + 0][r] = a.x; As[kk + 1][r] = a.y;
            As[kk + 2][r] = a.z; As[kk + 3][r] = a.w;
        }
        // Stage B tile (16 k x 64 cols)
#pragma unroll
        for (int i = 0; i < 2; i++) {
            int v  = tid + i * 128;      // float4 id 0..255
            int kk = v >> 4;
            int n4 = (v & 15) * 4;
            float4 b = make_float4(0.f, 0.f, 0.f, 0.f);
            if (n0 + n4 < Ncol)
                b = *reinterpret_cast<const float4*>(B + (size_t)(k0 + kk) * ldb + n0 + n4);
            *reinterpret_cast<float4*>(&Bs[kk][n4]) = b;
        }
        __syncthreads();

#pragma unroll
        for (int kk = 0; kk < 16; kk++) {
            float4 a0 = *reinterpret_cast<const float4*>(&As[kk][ty * 8]);
            float4 a1 = *reinterpret_cast<const float4*>(&As[kk][ty * 8 + 4]);
            float4 b0 = *reinterpret_cast<const float4*>(&Bs[kk][tx * 8]);
            float4 b1 = *reinterpret_cast<const float4*>(&Bs[kk][tx * 8 + 4]);
            float a[8] = {a0.x, a0.y, a0.z, a0.w, a1.x, a1.y, a1.z, a1.w};
            float b[8] = {b0.x, b0.y, b0.z, b0.w, b1.x, b1.y, b1.z, b1.w};
#pragma unroll
            for (int i = 0; i < 8; i++)
#pragma unroll
                for (int j = 0; j < 8; j++)
                    acc[i][j] = fmaf(a[i], b[j], acc[i][j]);
        }
        __syncthreads();
    }

    // Epilogue
#pragma unroll
    for (int i = 0; i < 8; i++) {
        int m = m0 + ty * 8 + i;
        if (m >= M) continue;
#pragma unroll
        for (int j = 0; j < 8; j++) {
            int n = n0 + tx * 8 + j;
            if (n >= Ncol) continue;
            float v = acc[i][j];
            if (BIAS) v += bias[n];
            if (RELU) v = fmaxf(v, 0.f);
            if (RES)  v += res[(size_t)m * ldres + n];
            C[(size_t)m * ldc + n] = v;
        }
    }
}

// ---------------------------------------------------------------------------
// Gather-sum: out[i,c] (+=) sum_{k=k0..k0+nk-1} mask[i,k] ? t[nbr[i,k], (k-k0)*CO + c]
// FINAL: add (optional partial) + bias (+ relu) (+ residual x slice) and store.
// Block = 256 threads = (256/CO) points x CO channels. mask==0 skips the load
// entirely (uniform branch per warp) -> halves random-gather traffic.
// ---------------------------------------------------------------------------
template<int CO, bool RELU, bool RES, bool FINAL, bool PART>
__global__ __launch_bounds__(256)
void gather_kernel(const float* __restrict__ t, int ldt, int k0, int nk,
                   const int* __restrict__ nbr, const int* __restrict__ mask,
                   const float* __restrict__ bias,
                   float* __restrict__ out, int ldo, int ocol,
                   const float* __restrict__ res,
                   const float* __restrict__ partial, int N)
{
    constexpr int PP = 256 / CO;
    __shared__ int s_nbr[PP * 27];
    __shared__ int s_msk[PP * 27];

    const int tid = threadIdx.x;
    const int p0  = blockIdx.x * PP;

    if (tid < PP * 27) {
        int pt = tid / 27, kk = tid % 27;
        int g = p0 + pt;
        s_nbr[tid] = (g < N) ? nbr[(size_t)g * 27 + kk] : 0;
        s_msk[tid] = (g < N) ? mask[(size_t)g * 27 + kk] : 0;
    }
    __syncthreads();

    const int p  = tid / CO;
    const int c  = tid % CO;
    const int gp = p0 + p;
    if (gp >= N) return;

    float acc = 0.f;
    for (int k = 0; k < nk; k++) {
        int kk = k0 + k;
        if (s_msk[p * 27 + kk])
            acc += t[(size_t)s_nbr[p * 27 + kk] * ldt + k * CO + c];
    }

    if (FINAL) {
        float v = acc;
        if (PART) v += partial[(size_t)gp * CO + c];
        v += bias[c];
        if (RELU) v = fmaxf(v, 0.f);
        if (RES)  v += res[(size_t)gp * 128 + ocol + c];
        out[(size_t)gp * ldo + ocol + c] = v;
    } else {
        out[(size_t)gp * ldo + ocol + c] = acc;   // raw partial
    }
}

// ---------------------------------------------------------------------------
// Launch
// ---------------------------------------------------------------------------
extern "C" void kernel_launch(void* const* d_in, const int* in_sizes, int n_in,
                              void* d_out, int out_size)
{
    const float* x    = (const float*)d_in[0];
    const int*   nbr  = (const int*)  d_in[1];
    const int*   mask = (const int*)  d_in[2];   // jnp bool -> int32 in harness
    const float* W00  = (const float*)d_in[3];
    const float* b00  = (const float*)d_in[4];
    const float* W01  = (const float*)d_in[5];
    const float* b01  = (const float*)d_in[6];
    const float* W02  = (const float*)d_in[7];
    const float* b02  = (const float*)d_in[8];
    const float* W10  = (const float*)d_in[9];
    const float* b10  = (const float*)d_in[10];
    const float* W11  = (const float*)d_in[11];
    const float* b11  = (const float*)d_in[12];
    float* out = (float*)d_out;

    const int N = in_sizes[0] / 128;

    float *t, *h0, *h1, *h0b, *p64, *w10t, *w01t, *w11t;
    cudaGetSymbolAddress((void**)&t,    g_t);
    cudaGetSymbolAddress((void**)&h0,   g_h0);
    cudaGetSymbolAddress((void**)&h1,   g_h1);
    cudaGetSymbolAddress((void**)&h0b,  g_h0b);
    cudaGetSymbolAddress((void**)&p64,  g_p64);
    cudaGetSymbolAddress((void**)&w10t, g_W10t);
    cudaGetSymbolAddress((void**)&w01t, g_W01t);
    cudaGetSymbolAddress((void**)&w11t, g_W11t);

    prep_w<<<432, 256>>>(W10, W01, W11);

    const dim3 blk(128);
    const int mt = (N + 127) / 128;

    // --- branch 1 first conv: t = x @ W10cat ; h1 = relu(gather-sum + b10)
    sgemm_kernel<false,false,false><<<dim3(mt, 14), blk>>>(
        x, 128, w10t, 864, t, 864, N, 128, 864, nullptr, nullptr, 0);
    gather_kernel<32,true,false,true,false><<<(N + 7) / 8, 256>>>(
        t, 864, 0, 27, nbr, mask, b10, h1, 32, 0, nullptr, nullptr, N);

    // --- branch 0: h0 = relu(x @ W00 + b00)
    sgemm_kernel<true,true,false><<<dim3(mt, 1), blk>>>(
        x, 128, W00, 32, h0, 32, N, 128, 32, b00, nullptr, 0);

    // --- branch 0 conv3: t = h0 @ W01cat ; h0b = relu(gather-sum + b01)
    sgemm_kernel<false,false,false><<<dim3(mt, 14), blk>>>(
        h0, 32, w01t, 864, t, 864, N, 32, 864, nullptr, nullptr, 0);
    gather_kernel<32,true,false,true,false><<<(N + 7) / 8, 256>>>(
        t, 864, 0, 27, nbr, mask, b01, h0b, 32, 0, nullptr, nullptr, N);

    // --- out[:, 0:64] = h0b @ W02 + b02 + x[:, 0:64]
    sgemm_kernel<true,false,true><<<dim3(mt, 1), blk>>>(
        h0b, 32, W02, 64, out, 128, N, 32, 64, b02, x, 128);

    // --- branch 1 second conv (split K=27 -> 14 + 13 to fit scratch):
    // pass A: k in [0,14): t = h1 @ W11cat[:, 0:896] ; partial = gather-sum
    sgemm_kernel<false,false,false><<<dim3(mt, 14), blk>>>(
        h1, 32, w11t, 1728, t, 896, N, 32, 896, nullptr, nullptr, 0);
    gather_kernel<64,false,false,false,false><<<(N + 3) / 4, 256>>>(
        t, 896, 0, 14, nbr, mask, nullptr, p64, 64, 0, nullptr, nullptr, N);
    // pass B: k in [14,27): t = h1 @ W11cat[:, 896:1728] ;
    // out[:, 64:128] = partial + gather-sum + b11 + x[:, 64:128]
    sgemm_kernel<false,false,false><<<dim3(mt, 13), blk>>>(
        h1, 32, w11t + 896, 1728, t, 832, N, 32, 832, nullptr, nullptr, 0);
    gather_kernel<64,false,true,true,true><<<(N + 3) / 4, 256>>>(
        t, 832, 14, 13, nbr, mask, b11, out, 128, 64, x, p64, N);
}

// round 7
// speedup vs baseline: 1.9516x; 1.9516x over previous
#include <cuda_runtime.h>
#include <cuda_bf16.h>
#include <cstdint>

// ---------------------------------------------------------------------------
// InceptionResNet sparse-conv block.
//   t = f @ concat_k(W_k)  via warp-level mma.sync bf16 (split-fp32:
//   hi*hi + hi*lo + lo*hi, fp32 accum)  [tcgen05 unavailable: harness PTX
//   targets compute_103 without the 'a' suffix]
//   conv3(f)[i] = sum_k mask[i,k] * t[nbr[i,k], k*Cout:(k+1)*Cout]
// ---------------------------------------------------------------------------

#define NPTS 500000

__device__ float g_t[448000000];      // [N, <=896] GEMM scratch (1.79 GB)
__device__ float g_h0 [NPTS * 32];
__device__ float g_h1 [NPTS * 32];
__device__ float g_h0b[NPTS * 32];
__device__ float g_p64[NPTS * 64];

// B fragment images: per tile, layout [s(k16)][f(n8)][lane][hi b0,b1, lo b0,b1]
// (one uint4 per lane). Tile stride = NS*8*32 uint4.
__device__ uint4 g_B10i[14 * 8 * 8 * 32];   // W10: K=128 -> NS=8, 14 n-tiles
__device__ uint4 g_B01i[14 * 2 * 8 * 32];   // W01: K=32  -> NS=2, 14 n-tiles
__device__ uint4 g_B11i[27 * 2 * 8 * 32];   // W11: K=32  -> NS=2, 27 n-tiles

// ---------------------------------------------------------------------------
// helpers
// ---------------------------------------------------------------------------
__device__ __forceinline__ void splitf(float x, uint16_t& h, uint16_t& l) {
    __nv_bfloat16 hb = __float2bfloat16(x);
    __nv_bfloat16 lb = __float2bfloat16(x - __bfloat162float(hb));
    h = __bfloat16_as_ushort(hb);
    l = __bfloat16_as_ushort(lb);
}

__device__ __forceinline__ void mma16816(float* c, const uint32_t* a,
                                         uint32_t b0, uint32_t b1) {
    asm volatile(
        "mma.sync.aligned.m16n8k16.row.col.f32.bf16.bf16.f32 "
        "{%0,%1,%2,%3}, {%4,%5,%6,%7}, {%8,%9}, {%0,%1,%2,%3};"
        : "+f"(c[0]), "+f"(c[1]), "+f"(c[2]), "+f"(c[3])
        : "r"(a[0]), "r"(a[1]), "r"(a[2]), "r"(a[3]), "r"(b0), "r"(b1));
}

// ---------------------------------------------------------------------------
// Weight prep: build B fragment images.
// For mma.row.col, B frag (k16 x n8): lane l (g=l>>2, t=l&3) holds
//   b0 = { B[16s+2t][n], B[16s+2t+1][n] },  b1 = { B[16s+2t+8][n], ..+9 },
// with n = j*64 + f*8 + g and B[k][n] = W[k27][k][c] (n = k27*Co + c).
// ---------------------------------------------------------------------------
template<int CIN, int CO>
__device__ __forceinline__ void prep_one(const float* __restrict__ W,
                                         uint4* __restrict__ img,
                                         int ntiles, int idx) {
    const int NS = CIN / 16;
    const int total = ntiles * NS * 8 * 32;
    if (idx >= total) return;
    int l = idx & 31, f = (idx >> 5) & 7, s = (idx >> 8) % NS, j = idx / (NS * 256);
    int g = l >> 2, t = l & 3;
    int n = j * 64 + f * 8 + g;
    int k27 = n / CO, c = n % CO;
    bool vn = (n < 27 * CO);
    uint16_t h[4], lo[4];
    int kb[4] = {16 * s + 2 * t, 16 * s + 2 * t + 1, 16 * s + 2 * t + 8, 16 * s + 2 * t + 9};
#pragma unroll
    for (int i = 0; i < 4; i++) {
        float v = vn ? W[((size_t)k27 * CIN + kb[i]) * CO + c] : 0.f;
        splitf(v, h[i], lo[i]);
    }
    uint4 r;
    r.x = ((uint32_t)h[1] << 16)  | h[0];
    r.y = ((uint32_t)h[3] << 16)  | h[2];
    r.z = ((uint32_t)lo[1] << 16) | lo[0];
    r.w = ((uint32_t)lo[3] << 16) | lo[2];
    img[idx] = r;
}

__global__ void prep_img(const float* __restrict__ W10,
                         const float* __restrict__ W01,
                         const float* __restrict__ W11)
{
    int idx = blockIdx.x * 256 + threadIdx.x;
    prep_one<128, 32>(W10, g_B10i, 14, idx);
    prep_one<32, 32>(W01, g_B01i, 14, idx);
    prep_one<32, 64>(W11, g_B11i, 27, idx);
}

// ---------------------------------------------------------------------------
// Tensor-core GEMM: C[M, ntiles*64] = A[M, KDIM] @ B (pre-imaged, split bf16)
// CTA = 128 threads (4 warps), m-tile = 128 rows; warp w owns rows
// [32w, 32w+32) = m16-blocks 2w, 2w+1. Loops over 64-col n-tiles.
//
// smem A fragment image: [s][mblk(8)][lane][4 hi u32][4 lo u32] (uint4 pairs)
// smem B fragment image: [s][f(8)][lane][uint4 (hi b0,b1, lo b0,b1)]
// ---------------------------------------------------------------------------
template<int KDIM>
__global__ __launch_bounds__(128)
void tcmm_kernel(const float* __restrict__ A, int lda,
                 const uint4* __restrict__ Bimg,
                 float* __restrict__ C, int ldc, int M, int ntiles)
{
    constexpr int NS = KDIM / 16;
    constexpr int ASZ4 = NS * 8 * 32 * 2;   // A image in uint4 units
    constexpr int BSZ4 = NS * 8 * 32;       // B image in uint4 units

    extern __shared__ uint4 smem4[];
    uint4* Aimg = smem4;                    // [ASZ4]
    uint4* Bsh  = smem4 + ASZ4;             // [BSZ4]
    uint32_t* Aimg32 = reinterpret_cast<uint32_t*>(Aimg);

    const int tid  = threadIdx.x;
    const int wid  = tid >> 5;
    const int lane = tid & 31;
    const int m0   = blockIdx.x * 128;

    // ---- stage A (one row per thread) into fragment image, split hi/lo ----
    {
        const int r = tid;
        const bool vrow = (m0 + r) < M;
        const float* ap = A + (size_t)(m0 + r) * lda;
        const int mblk = r >> 4;
        const int half = (r >> 3) & 1;
        const int g    = r & 7;
#pragma unroll
        for (int q = 0; q < KDIM / 4; q++) {
            float4 a = vrow ? *reinterpret_cast<const float4*>(ap + q * 4)
                            : make_float4(0.f, 0.f, 0.f, 0.f);
            uint16_t h0, l0, h1, l1, h2, l2, h3, l3;
            splitf(a.x, h0, l0); splitf(a.y, h1, l1);
            splitf(a.z, h2, l2); splitf(a.w, h3, l3);
            uint32_t hiA = ((uint32_t)h1 << 16) | h0, loA = ((uint32_t)l1 << 16) | l0;
            uint32_t hiB = ((uint32_t)h3 << 16) | h2, loB = ((uint32_t)l3 << 16) | l2;
            // pair indices
            int k = q * 4;
            int s  = k >> 4;
            int pA = (k >> 1) & 7;        // pair for elements x,y
            int pB = pA + 1;              // pair for elements z,w
            int laneA = g * 4 + (pA & 3), slotA = half + ((pA >> 2) << 1);
            int laneB = g * 4 + (pB & 3), slotB = half + ((pB >> 2) << 1);
            uint32_t baseA = (((s * 8 + mblk) * 32 + laneA) * 2) * 4;
            uint32_t baseB = (((s * 8 + mblk) * 32 + laneB) * 2) * 4;
            Aimg32[baseA + slotA]     = hiA;   // hi slots 0..3
            Aimg32[baseA + 4 + slotA] = loA;   // lo slots 4..7
            Aimg32[baseB + slotB]     = hiB;
            Aimg32[baseB + 4 + slotB] = loB;
        }
    }

    const int mb0 = 2 * wid;      // first m16 block of this warp
    const int g   = lane >> 2;
    const int t   = lane & 3;

    // ---- n-tile loop ----
    for (int j = 0; j < ntiles; j++) {
        __syncthreads();          // previous tile's smem reads done (also A staging)
        {
            const uint4* src = Bimg + (size_t)j * BSZ4;
#pragma unroll 4
            for (int i = tid; i < BSZ4; i += 128) Bsh[i] = src[i];
        }
        __syncthreads();

        float acc[2][8][4];
#pragma unroll
        for (int mb = 0; mb < 2; mb++)
#pragma unroll
            for (int f = 0; f < 8; f++)
#pragma unroll
                for (int i = 0; i < 4; i++) acc[mb][f][i] = 0.f;

#pragma unroll
        for (int s = 0; s < NS; s++) {
            uint4 ah[2], al[2];
#pragma unroll
            for (int mb = 0; mb < 2; mb++) {
                int base = ((s * 8 + mb0 + mb) * 32 + lane) * 2;
                ah[mb] = Aimg[base];
                al[mb] = Aimg[base + 1];
            }
#pragma unroll
            for (int f = 0; f < 8; f++) {
                uint4 b = Bsh[(s * 8 + f) * 32 + lane];
#pragma unroll
                for (int mb = 0; mb < 2; mb++) {
                    const uint32_t* ahp = reinterpret_cast<const uint32_t*>(&ah[mb]);
                    const uint32_t* alp = reinterpret_cast<const uint32_t*>(&al[mb]);
                    mma16816(acc[mb][f], ahp, b.x, b.y);   // hi*hi
                    mma16816(acc[mb][f], ahp, b.z, b.w);   // hi*lo
                    mma16816(acc[mb][f], alp, b.x, b.y);   // lo*hi
                }
            }
        }

        // ---- epilogue: C[m][n], rows g / g+8 of each m16 block ----
#pragma unroll
        for (int mb = 0; mb < 2; mb++) {
            int mrow0 = m0 + (mb0 + mb) * 16 + g;
#pragma unroll
            for (int f = 0; f < 8; f++) {
                int ncol = j * 64 + f * 8 + 2 * t;
                if (mrow0 < M)
                    *reinterpret_cast<float2*>(C + (size_t)mrow0 * ldc + ncol) =
                        make_float2(acc[mb][f][0], acc[mb][f][1]);
                if (mrow0 + 8 < M)
                    *reinterpret_cast<float2*>(C + (size_t)(mrow0 + 8) * ldc + ncol) =
                        make_float2(acc[mb][f][2], acc[mb][f][3]);
            }
        }
    }
}

// ---------------------------------------------------------------------------
// fp32 SGEMM for the small 1x1 convs (W00, W02) — proven R0 kernel.
// ---------------------------------------------------------------------------
template<bool BIAS, bool RELU, bool RES>
__global__ __launch_bounds__(128)
void sgemm_kernel(const float* __restrict__ A, int lda,
                  const float* __restrict__ B, int ldb,
                  float* __restrict__ C, int ldc,
                  int M, int K, int Ncol,
                  const float* __restrict__ bias,
                  const float* __restrict__ res, int ldres)
{
    __shared__ float As[16][128];
    __shared__ float Bs[16][64];

    const int tid = threadIdx.x;
    const int tx  = tid & 7;
    const int ty  = tid >> 3;
    const int m0  = blockIdx.x * 128;
    const int n0  = blockIdx.y * 64;

    float acc[8][8];
#pragma unroll
    for (int i = 0; i < 8; i++)
#pragma unroll
        for (int j = 0; j < 8; j++) acc[i][j] = 0.f;

    for (int k0 = 0; k0 < K; k0 += 16) {
#pragma unroll
        for (int i = 0; i < 4; i++) {
            int v  = tid + i * 128;
            int r  = v >> 2;
            int kk = (v & 3) * 4;
            int m  = m0 + r;
            float4 a = make_float4(0.f, 0.f, 0.f, 0.f);
            if (m < M)
                a = *reinterpret_cast<const float4*>(A + (size_t)m * lda + k0 + kk);
            As[kk + 0][r] = a.x; As[kk + 1][r] = a.y;
            As[kk + 2][r] = a.z; As[kk + 3][r] = a.w;
        }
#pragma unroll
        for (int i = 0; i < 2; i++) {
            int v  = tid + i * 128;
            int kk = v >> 4;
            int n4 = (v & 15) * 4;
            float4 b = make_float4(0.f, 0.f, 0.f, 0.f);
            if (n0 + n4 < Ncol)
                b = *reinterpret_cast<const float4*>(B + (size_t)(k0 + kk) * ldb + n0 + n4);
            *reinterpret_cast<float4*>(&Bs[kk][n4]) = b;
        }
        __syncthreads();

#pragma unroll
        for (int kk = 0; kk < 16; kk++) {
            float4 a0 = *reinterpret_cast<const float4*>(&As[kk][ty * 8]);
            float4 a1 = *reinterpret_cast<const float4*>(&As[kk][ty * 8 + 4]);
            float4 b0 = *reinterpret_cast<const float4*>(&Bs[kk][tx * 8]);
            float4 b1 = *reinterpret_cast<const float4*>(&Bs[kk][tx * 8 + 4]);
            float a[8] = {a0.x, a0.y, a0.z, a0.w, a1.x, a1.y, a1.z, a1.w};
            float b[8] = {b0.x, b0.y, b0.z, b0.w, b1.x, b1.y, b1.z, b1.w};
#pragma unroll
            for (int i = 0; i < 8; i++)
#pragma unroll
                for (int j = 0; j < 8; j++)
                    acc[i][j] = fmaf(a[i], b[j], acc[i][j]);
        }
        __syncthreads();
    }

#pragma unroll
    for (int i = 0; i < 8; i++) {
        int m = m0 + ty * 8 + i;
        if (m >= M) continue;
#pragma unroll
        for (int j = 0; j < 8; j++) {
            int n = n0 + tx * 8 + j;
            if (n >= Ncol) continue;
            float v = acc[i][j];
            if (BIAS) v += bias[n];
            if (RELU) v = fmaxf(v, 0.f);
            if (RES)  v += res[(size_t)m * ldres + n];
            C[(size_t)m * ldc + n] = v;
        }
    }
}

// ---------------------------------------------------------------------------
// Gather-sum (unchanged from passing R5)
// ---------------------------------------------------------------------------
template<int CO, bool RELU, bool RES, bool FINAL, bool PART>
__global__ __launch_bounds__(256)
void gather_kernel(const float* __restrict__ t, int ldt, int k0, int nk,
                   const int* __restrict__ nbr, const int* __restrict__ mask,
                   const float* __restrict__ bias,
                   float* __restrict__ out, int ldo, int ocol,
                   const float* __restrict__ res,
                   const float* __restrict__ partial, int N)
{
    constexpr int PP = 256 / CO;
    __shared__ int s_nbr[PP * 27];
    __shared__ int s_msk[PP * 27];

    const int tid = threadIdx.x;
    const int p0  = blockIdx.x * PP;

    if (tid < PP * 27) {
        int pt = tid / 27, kk = tid % 27;
        int g = p0 + pt;
        s_nbr[tid] = (g < N) ? nbr[(size_t)g * 27 + kk] : 0;
        s_msk[tid] = (g < N) ? mask[(size_t)g * 27 + kk] : 0;
    }
    __syncthreads();

    const int p  = tid / CO;
    const int c  = tid % CO;
    const int gp = p0 + p;
    if (gp >= N) return;

    float acc = 0.f;
    for (int k = 0; k < nk; k++) {
        int kk = k0 + k;
        if (s_msk[p * 27 + kk])
            acc += t[(size_t)s_nbr[p * 27 + kk] * ldt + k * CO + c];
    }

    if (FINAL) {
        float v = acc;
        if (PART) v += partial[(size_t)gp * CO + c];
        v += bias[c];
        if (RELU) v = fmaxf(v, 0.f);
        if (RES)  v += res[(size_t)gp * 128 + ocol + c];
        out[(size_t)gp * ldo + ocol + c] = v;
    } else {
        out[(size_t)gp * ldo + ocol + c] = acc;
    }
}

// ---------------------------------------------------------------------------
// Launch
// ---------------------------------------------------------------------------
extern "C" void kernel_launch(void* const* d_in, const int* in_sizes, int n_in,
                              void* d_out, int out_size)
{
    const float* x    = (const float*)d_in[0];
    const int*   nbr  = (const int*)  d_in[1];
    const int*   mask = (const int*)  d_in[2];
    const float* W00  = (const float*)d_in[3];
    const float* b00  = (const float*)d_in[4];
    const float* W01  = (const float*)d_in[5];
    const float* b01  = (const float*)d_in[6];
    const float* W02  = (const float*)d_in[7];
    const float* b02  = (const float*)d_in[8];
    const float* W10  = (const float*)d_in[9];
    const float* b10  = (const float*)d_in[10];
    const float* W11  = (const float*)d_in[11];
    const float* b11  = (const float*)d_in[12];
    float* out = (float*)d_out;

    const int N = in_sizes[0] / 128;

    float *t, *h0, *h1, *h0b, *p64;
    uint4 *B10i, *B01i, *B11i;
    cudaGetSymbolAddress((void**)&t,    g_t);
    cudaGetSymbolAddress((void**)&h0,   g_h0);
    cudaGetSymbolAddress((void**)&h1,   g_h1);
    cudaGetSymbolAddress((void**)&h0b,  g_h0b);
    cudaGetSymbolAddress((void**)&p64,  g_p64);
    cudaGetSymbolAddress((void**)&B10i, g_B10i);
    cudaGetSymbolAddress((void**)&B01i, g_B01i);
    cudaGetSymbolAddress((void**)&B11i, g_B11i);

    // smem: A image NS*8*32*32B + B image NS*8*32*16B
    const int SMEM128 = 8 * 8 * 32 * 32 + 8 * 8 * 32 * 16;  // 98304
    const int SMEM32  = 2 * 8 * 32 * 32 + 2 * 8 * 32 * 16;  // 24576
    cudaFuncSetAttribute(tcmm_kernel<128>, cudaFuncAttributeMaxDynamicSharedMemorySize, SMEM128);
    cudaFuncSetAttribute(tcmm_kernel<32>,  cudaFuncAttributeMaxDynamicSharedMemorySize, SMEM32);

    prep_img<<<112, 256>>>(W10, W01, W11);

    const int mt = (N + 127) / 128;

    // --- branch 1 first conv: t = x @ W10cat ; h1 = relu(gather + b10)
    tcmm_kernel<128><<<mt, 128, SMEM128>>>(x, 128, B10i, t, 896, N, 14);
    gather_kernel<32,true,false,true,false><<<(N + 7) / 8, 256>>>(
        t, 896, 0, 27, nbr, mask, b10, h1, 32, 0, nullptr, nullptr, N);

    // --- branch 0: h0 = relu(x @ W00 + b00)
    sgemm_kernel<true,true,false><<<dim3(mt, 1), 128>>>(
        x, 128, W00, 32, h0, 32, N, 128, 32, b00, nullptr, 0);

    // --- branch 0 conv3: t = h0 @ W01cat ; h0b = relu(gather + b01)
    tcmm_kernel<32><<<mt, 128, SMEM32>>>(h0, 32, B01i, t, 896, N, 14);
    gather_kernel<32,true,false,true,false><<<(N + 7) / 8, 256>>>(
        t, 896, 0, 27, nbr, mask, b01, h0b, 32, 0, nullptr, nullptr, N);

    // --- out[:, 0:64] = h0b @ W02 + b02 + x[:, 0:64]
    sgemm_kernel<true,false,true><<<dim3(mt, 1), 128>>>(
        h0b, 32, W02, 64, out, 128, N, 32, 64, b02, x, 128);

    // --- branch 1 second conv, split K=27 -> 14 + 13:
    tcmm_kernel<32><<<mt, 128, SMEM32>>>(h1, 32, B11i, t, 896, N, 14);
    gather_kernel<64,false,false,false,false><<<(N + 3) / 4, 256>>>(
        t, 896, 0, 14, nbr, mask, nullptr, p64, 64, 0, nullptr, nullptr, N);

    tcmm_kernel<32><<<mt, 128, SMEM32>>>(h1, 32, B11i + (size_t)14 * 2 * 8 * 32, t, 832, N, 13);
    gather_kernel<64,false,true,true,true><<<(N + 3) / 4, 256>>>(
        t, 832, 14, 13, nbr, mask, b11, out, 128, 64, x, p64, N);
}

// round 10
// speedup vs baseline: 1.9811x; 1.0151x over previous
#include <cuda_runtime.h>
#include <cuda_bf16.h>
#include <cstdint>

// ---------------------------------------------------------------------------
// InceptionResNet sparse-conv block.
//   t = f @ concat_k(W_k)  via warp-level mma.sync bf16 (split-fp32:
//   hi*hi + hi*lo + lo*hi, fp32 accum)  [tcgen05 unavailable: harness PTX
//   targets compute_103 without the 'a' suffix]
//   conv3(f)[i] = sum_k mask[i,k] * t[nbr[i,k], k*Cout:(k+1)*Cout]
// R8: tcmm mainloop rebuilt — 8 warps/CTA + double-buffered cp.async B.
// ---------------------------------------------------------------------------

#define NPTS 500000

__device__ float g_t[448000000];      // [N, <=896] GEMM scratch (1.79 GB)
__device__ float g_h0 [NPTS * 32];
__device__ float g_h1 [NPTS * 32];
__device__ float g_h0b[NPTS * 32];
__device__ float g_p64[NPTS * 64];

// B fragment images: per tile, layout [s(k16)][f(n8)][lane][hi b0,b1, lo b0,b1]
__device__ uint4 g_B10i[14 * 8 * 8 * 32];   // W10: K=128 -> NS=8, 14 n-tiles
__device__ uint4 g_B01i[14 * 2 * 8 * 32];   // W01: K=32  -> NS=2, 14 n-tiles
__device__ uint4 g_B11i[27 * 2 * 8 * 32];   // W11: K=32  -> NS=2, 27 n-tiles

// ---------------------------------------------------------------------------
// helpers
// ---------------------------------------------------------------------------
__device__ __forceinline__ void splitf(float x, uint16_t& h, uint16_t& l) {
    __nv_bfloat16 hb = __float2bfloat16(x);
    __nv_bfloat16 lb = __float2bfloat16(x - __bfloat162float(hb));
    h = __bfloat16_as_ushort(hb);
    l = __bfloat16_as_ushort(lb);
}

__device__ __forceinline__ void mma16816(float* c, const uint32_t* a,
                                         uint32_t b0, uint32_t b1) {
    asm volatile(
        "mma.sync.aligned.m16n8k16.row.col.f32.bf16.bf16.f32 "
        "{%0,%1,%2,%3}, {%4,%5,%6,%7}, {%8,%9}, {%0,%1,%2,%3};"
        : "+f"(c[0]), "+f"(c[1]), "+f"(c[2]), "+f"(c[3])
        : "r"(a[0]), "r"(a[1]), "r"(a[2]), "r"(a[3]), "r"(b0), "r"(b1));
}

__device__ __forceinline__ void cp_async16(void* sdst, const void* gsrc) {
    uint32_t s;
    asm("{ .reg .u64 t; cvta.to.shared.u64 t, %1; cvt.u32.u64 %0, t; }"
        : "=r"(s) : "l"(sdst));
    asm volatile("cp.async.ca.shared.global [%0], [%1], 16;" :: "r"(s), "l"(gsrc));
}
__device__ __forceinline__ void cp_commit() {
    asm volatile("cp.async.commit_group;" ::: "memory");
}
__device__ __forceinline__ void cp_wait0() {
    asm volatile("cp.async.wait_group 0;" ::: "memory");
}

// ---------------------------------------------------------------------------
// Weight prep: B fragment images (unchanged from R7).
// lane l (g=l>>2, t=l&3): b0={B[16s+2t][n],B[16s+2t+1][n]}, b1={..+8,..+9},
// n = j*64 + f*8 + g, B[k][n] = W[k27][k][c] (n = k27*Co + c).
// ---------------------------------------------------------------------------
template<int CIN, int CO>
__device__ __forceinline__ void prep_one(const float* __restrict__ W,
                                         uint4* __restrict__ img,
                                         int ntiles, int idx) {
    const int NS = CIN / 16;
    const int total = ntiles * NS * 8 * 32;
    if (idx >= total) return;
    int l = idx & 31, f = (idx >> 5) & 7, s = (idx >> 8) % NS, j = idx / (NS * 256);
    int g = l >> 2, t = l & 3;
    int n = j * 64 + f * 8 + g;
    int k27 = n / CO, c = n % CO;
    bool vn = (n < 27 * CO);
    uint16_t h[4], lo[4];
    int kb[4] = {16 * s + 2 * t, 16 * s + 2 * t + 1, 16 * s + 2 * t + 8, 16 * s + 2 * t + 9};
#pragma unroll
    for (int i = 0; i < 4; i++) {
        float v = vn ? W[((size_t)k27 * CIN + kb[i]) * CO + c] : 0.f;
        splitf(v, h[i], lo[i]);
    }
    uint4 r;
    r.x = ((uint32_t)h[1] << 16)  | h[0];
    r.y = ((uint32_t)h[3] << 16)  | h[2];
    r.z = ((uint32_t)lo[1] << 16) | lo[0];
    r.w = ((uint32_t)lo[3] << 16) | lo[2];
    img[idx] = r;
}

__global__ void prep_img(const float* __restrict__ W10,
                         const float* __restrict__ W01,
                         const float* __restrict__ W11)
{
    int idx = blockIdx.x * 256 + threadIdx.x;
    prep_one<128, 32>(W10, g_B10i, 14, idx);
    prep_one<32, 32>(W01, g_B01i, 14, idx);
    prep_one<32, 64>(W11, g_B11i, 27, idx);
}

// ---------------------------------------------------------------------------
// Tensor-core GEMM: C[M, ntiles*64] = A[M, KDIM] @ B (pre-imaged, split bf16)
// CTA = 256 threads (8 warps); warp w owns m16 block w (rows 16w..16w+15).
// B tiles double-buffered via cp.async; one __syncthreads per tile.
//
// smem A image: [s][mblk(8)][lane][4 hi u32][4 lo u32]
// smem B bufs : 2 x [s][f(8)][lane][uint4]
// ---------------------------------------------------------------------------
template<int KDIM>
__global__ __launch_bounds__(256)
void tcmm_kernel(const float* __restrict__ A, int lda,
                 const uint4* __restrict__ Bimg,
                 float* __restrict__ C, int ldc, int M, int ntiles)
{
    constexpr int NS = KDIM / 16;
    constexpr int ASZ4 = NS * 8 * 32 * 2;   // A image (uint4 units)
    constexpr int BSZ4 = NS * 8 * 32;       // one B buffer (uint4 units)

    extern __shared__ uint4 smem4[];
    uint4* Aimg = smem4;
    uint4* Bbuf0 = smem4 + ASZ4;
    uint4* Bbuf1 = smem4 + ASZ4 + BSZ4;
    uint32_t* Aimg32 = reinterpret_cast<uint32_t*>(Aimg);

    const int tid  = threadIdx.x;
    const int wid  = tid >> 5;
    const int lane = tid & 31;
    const int m0   = blockIdx.x * 128;

    // ---- stage A: 256 threads, each stages half a row ----
    {
        const int r = tid & 127;
        const int khalf = tid >> 7;               // 0/1
        constexpr int QPT = KDIM / 8;             // float4s per thread
        const bool vrow = (m0 + r) < M;
        const float* ap = A + (size_t)(m0 + r) * lda;
        const int mblk = r >> 4;
        const int half = (r >> 3) & 1;
        const int g    = r & 7;
#pragma unroll
        for (int qq = 0; qq < QPT; qq++) {
            int q = khalf * QPT + qq;
            float4 a = vrow ? *reinterpret_cast<const float4*>(ap + q * 4)
                            : make_float4(0.f, 0.f, 0.f, 0.f);
            uint16_t h0, l0, h1, l1, h2, l2, h3, l3;
            splitf(a.x, h0, l0); splitf(a.y, h1, l1);
            splitf(a.z, h2, l2); splitf(a.w, h3, l3);
            uint32_t hiA = ((uint32_t)h1 << 16) | h0, loA = ((uint32_t)l1 << 16) | l0;
            uint32_t hiB = ((uint32_t)h3 << 16) | h2, loB = ((uint32_t)l3 << 16) | l2;
            int k = q * 4;
            int s  = k >> 4;
            int pA = (k >> 1) & 7;
            int pB = pA + 1;
            int laneA = g * 4 + (pA & 3), slotA = half + ((pA >> 2) << 1);
            int laneB = g * 4 + (pB & 3), slotB = half + ((pB >> 2) << 1);
            uint32_t baseA = (((s * 8 + mblk) * 32 + laneA) * 2) * 4;
            uint32_t baseB = (((s * 8 + mblk) * 32 + laneB) * 2) * 4;
            Aimg32[baseA + slotA]     = hiA;
            Aimg32[baseA + 4 + slotA] = loA;
            Aimg32[baseB + slotB]     = hiB;
            Aimg32[baseB + 4 + slotB] = loB;
        }
    }

    // ---- prefetch B tile 0 ----
    {
        const uint4* src = Bimg;
#pragma unroll
        for (int i = 0; i < BSZ4 / 256; i++)
            cp_async16(&Bbuf0[tid + i * 256], &src[tid + i * 256]);
        cp_commit();
    }

    const int g = lane >> 2;
    const int t = lane & 3;

    for (int j = 0; j < ntiles; j++) {
        uint4* Bcur = (j & 1) ? Bbuf1 : Bbuf0;
        uint4* Bnxt = (j & 1) ? Bbuf0 : Bbuf1;

        cp_wait0();
        __syncthreads();   // B[j] landed; all warps done with Bnxt (tile j-1)

        if (j + 1 < ntiles) {
            const uint4* src = Bimg + (size_t)(j + 1) * BSZ4;
#pragma unroll
            for (int i = 0; i < BSZ4 / 256; i++)
                cp_async16(&Bnxt[tid + i * 256], &src[tid + i * 256]);
            cp_commit();
        } else {
            cp_commit();   // empty group keeps wait_group(0) well-defined
        }

        float acc[8][4];
#pragma unroll
        for (int f = 0; f < 8; f++)
#pragma unroll
            for (int i = 0; i < 4; i++) acc[f][i] = 0.f;

#pragma unroll
        for (int s = 0; s < NS; s++) {
            int base = ((s * 8 + wid) * 32 + lane) * 2;
            uint4 ah = Aimg[base];
            uint4 al = Aimg[base + 1];
            const uint32_t* ahp = reinterpret_cast<const uint32_t*>(&ah);
            const uint32_t* alp = reinterpret_cast<const uint32_t*>(&al);
#pragma unroll
            for (int f = 0; f < 8; f++) {
                uint4 b = Bcur[(s * 8 + f) * 32 + lane];
                mma16816(acc[f], ahp, b.x, b.y);   // hi*hi
                mma16816(acc[f], ahp, b.z, b.w);   // hi*lo
                mma16816(acc[f], alp, b.x, b.y);   // lo*hi
            }
        }

        // ---- epilogue: warp's 16 rows x 64 cols ----
        int mrow0 = m0 + wid * 16 + g;
#pragma unroll
        for (int f = 0; f < 8; f++) {
            int ncol = j * 64 + f * 8 + 2 * t;
            if (mrow0 < M)
                *reinterpret_cast<float2*>(C + (size_t)mrow0 * ldc + ncol) =
                    make_float2(acc[f][0], acc[f][1]);
            if (mrow0 + 8 < M)
                *reinterpret_cast<float2*>(C + (size_t)(mrow0 + 8) * ldc + ncol) =
                    make_float2(acc[f][2], acc[f][3]);
        }
    }
}

// ---------------------------------------------------------------------------
// fp32 SGEMM for the small 1x1 convs (W00, W02) — proven R0 kernel.
// ---------------------------------------------------------------------------
template<bool BIAS, bool RELU, bool RES>
__global__ __launch_bounds__(128)
void sgemm_kernel(const float* __restrict__ A, int lda,
                  const float* __restrict__ B, int ldb,
                  float* __restrict__ C, int ldc,
                  int M, int K, int Ncol,
                  const float* __restrict__ bias,
                  const float* __restrict__ res, int ldres)
{
    __shared__ float As[16][128];
    __shared__ float Bs[16][64];

    const int tid = threadIdx.x;
    const int tx  = tid & 7;
    const int ty  = tid >> 3;
    const int m0  = blockIdx.x * 128;
    const int n0  = blockIdx.y * 64;

    float acc[8][8];
#pragma unroll
    for (int i = 0; i < 8; i++)
#pragma unroll
        for (int j = 0; j < 8; j++) acc[i][j] = 0.f;

    for (int k0 = 0; k0 < K; k0 += 16) {
#pragma unroll
        for (int i = 0; i < 4; i++) {
            int v  = tid + i * 128;
            int r  = v >> 2;
            int kk = (v & 3) * 4;
            int m  = m0 + r;
            float4 a = make_float4(0.f, 0.f, 0.f, 0.f);
            if (m < M)
                a = *reinterpret_cast<const float4*>(A + (size_t)m * lda + k0 + kk);
            As[kk + 0][r] = a.x; As[kk + 1][r] = a.y;
            As[kk + 2][r] = a.z; As[kk + 3][r] = a.w;
        }
#pragma unroll
        for (int i = 0; i < 2; i++) {
            int v  = tid + i * 128;
            int kk = v >> 4;
            int n4 = (v & 15) * 4;
            float4 b = make_float4(0.f, 0.f, 0.f, 0.f);
            if (n0 + n4 < Ncol)
                b = *reinterpret_cast<const float4*>(B + (size_t)(k0 + kk) * ldb + n0 + n4);
            *reinterpret_cast<float4*>(&Bs[kk][n4]) = b;
        }
        __syncthreads();

#pragma unroll
        for (int kk = 0; kk < 16; kk++) {
            float4 a0 = *reinterpret_cast<const float4*>(&As[kk][ty * 8]);
            float4 a1 = *reinterpret_cast<const float4*>(&As[kk][ty * 8 + 4]);
            float4 b0 = *reinterpret_cast<const float4*>(&Bs[kk][tx * 8]);
            float4 b1 = *reinterpret_cast<const float4*>(&Bs[kk][tx * 8 + 4]);
            float a[8] = {a0.x, a0.y, a0.z, a0.w, a1.x, a1.y, a1.z, a1.w};
            float b[8] = {b0.x, b0.y, b0.z, b0.w, b1.x, b1.y, b1.z, b1.w};
#pragma unroll
            for (int i = 0; i < 8; i++)
#pragma unroll
                for (int j = 0; j < 8; j++)
                    acc[i][j] = fmaf(a[i], b[j], acc[i][j]);
        }
        __syncthreads();
    }

#pragma unroll
    for (int i = 0; i < 8; i++) {
        int m = m0 + ty * 8 + i;
        if (m >= M) continue;
#pragma unroll
        for (int j = 0; j < 8; j++) {
            int n = n0 + tx * 8 + j;
            if (n >= Ncol) continue;
            float v = acc[i][j];
            if (BIAS) v += bias[n];
            if (RELU) v = fmaxf(v, 0.f);
            if (RES)  v += res[(size_t)m * ldres + n];
            C[(size_t)m * ldc + n] = v;
        }
    }
}

// ---------------------------------------------------------------------------
// Gather-sum (unchanged from passing R7)
// ---------------------------------------------------------------------------
template<int CO, bool RELU, bool RES, bool FINAL, bool PART>
__global__ __launch_bounds__(256)
void gather_kernel(const float* __restrict__ t, int ldt, int k0, int nk,
                   const int* __restrict__ nbr, const int* __restrict__ mask,
                   const float* __restrict__ bias,
                   float* __restrict__ out, int ldo, int ocol,
                   const float* __restrict__ res,
                   const float* __restrict__ partial, int N)
{
    constexpr int PP = 256 / CO;
    __shared__ int s_nbr[PP * 27];
    __shared__ int s_msk[PP * 27];

    const int tid = threadIdx.x;
    const int p0  = blockIdx.x * PP;

    if (tid < PP * 27) {
        int pt = tid / 27, kk = tid % 27;
        int g = p0 + pt;
        s_nbr[tid] = (g < N) ? nbr[(size_t)g * 27 + kk] : 0;
        s_msk[tid] = (g < N) ? mask[(size_t)g * 27 + kk] : 0;
    }
    __syncthreads();

    const int p  = tid / CO;
    const int c  = tid % CO;
    const int gp = p0 + p;
    if (gp >= N) return;

    float acc = 0.f;
    for (int k = 0; k < nk; k++) {
        int kk = k0 + k;
        if (s_msk[p * 27 + kk])
            acc += t[(size_t)s_nbr[p * 27 + kk] * ldt + k * CO + c];
    }

    if (FINAL) {
        float v = acc;
        if (PART) v += partial[(size_t)gp * CO + c];
        v += bias[c];
        if (RELU) v = fmaxf(v, 0.f);
        if (RES)  v += res[(size_t)gp * 128 + ocol + c];
        out[(size_t)gp * ldo + ocol + c] = v;
    } else {
        out[(size_t)gp * ldo + ocol + c] = acc;
    }
}

// ---------------------------------------------------------------------------
// Launch
// ---------------------------------------------------------------------------
extern "C" void kernel_launch(void* const* d_in, const int* in_sizes, int n_in,
                              void* d_out, int out_size)
{
    const float* x    = (const float*)d_in[0];
    const int*   nbr  = (const int*)  d_in[1];
    const int*   mask = (const int*)  d_in[2];
    const float* W00  = (const float*)d_in[3];
    const float* b00  = (const float*)d_in[4];
    const float* W01  = (const float*)d_in[5];
    const float* b01  = (const float*)d_in[6];
    const float* W02  = (const float*)d_in[7];
    const float* b02  = (const float*)d_in[8];
    const float* W10  = (const float*)d_in[9];
    const float* b10  = (const float*)d_in[10];
    const float* W11  = (const float*)d_in[11];
    const float* b11  = (const float*)d_in[12];
    float* out = (float*)d_out;

    const int N = in_sizes[0] / 128;

    float *t, *h0, *h1, *h0b, *p64;
    uint4 *B10i, *B01i, *B11i;
    cudaGetSymbolAddress((void**)&t,    g_t);
    cudaGetSymbolAddress((void**)&h0,   g_h0);
    cudaGetSymbolAddress((void**)&h1,   g_h1);
    cudaGetSymbolAddress((void**)&h0b,  g_h0b);
    cudaGetSymbolAddress((void**)&p64,  g_p64);
    cudaGetSymbolAddress((void**)&B10i, g_B10i);
    cudaGetSymbolAddress((void**)&B01i, g_B01i);
    cudaGetSymbolAddress((void**)&B11i, g_B11i);

    // smem: A image NS*8*32*32B + 2 B buffers NS*8*32*16B each
    const int SMEM128 = 8 * 8 * 32 * 32 + 2 * 8 * 8 * 32 * 16;  // 131072
    const int SMEM32  = 2 * 8 * 32 * 32 + 2 * 2 * 8 * 32 * 16;  // 32768
    cudaFuncSetAttribute(tcmm_kernel<128>, cudaFuncAttributeMaxDynamicSharedMemorySize, SMEM128);
    cudaFuncSetAttribute(tcmm_kernel<32>,  cudaFuncAttributeMaxDynamicSharedMemorySize, SMEM32);

    prep_img<<<112, 256>>>(W10, W01, W11);

    const int mt = (N + 127) / 128;

    // --- branch 1 first conv: t = x @ W10cat ; h1 = relu(gather + b10)
    tcmm_kernel<128><<<mt, 256, SMEM128>>>(x, 128, B10i, t, 896, N, 14);
    gather_kernel<32,true,false,true,false><<<(N + 7) / 8, 256>>>(
        t, 896, 0, 27, nbr, mask, b10, h1, 32, 0, nullptr, nullptr, N);

    // --- branch 0: h0 = relu(x @ W00 + b00)
    sgemm_kernel<true,true,false><<<dim3(mt, 1), 128>>>(
        x, 128, W00, 32, h0, 32, N, 128, 32, b00, nullptr, 0);

    // --- branch 0 conv3: t = h0 @ W01cat ; h0b = relu(gather + b01)
    tcmm_kernel<32><<<mt, 256, SMEM32>>>(h0, 32, B01i, t, 896, N, 14);
    gather_kernel<32,true,false,true,false><<<(N + 7) / 8, 256>>>(
        t, 896, 0, 27, nbr, mask, b01, h0b, 32, 0, nullptr, nullptr, N);

    // --- out[:, 0:64] = h0b @ W02 + b02 + x[:, 0:64]
    sgemm_kernel<true,false,true><<<dim3(mt, 1), 128>>>(
        h0b, 32, W02, 64, out, 128, N, 32, 64, b02, x, 128);

    // --- branch 1 second conv, split K=27 -> 14 + 13:
    tcmm_kernel<32><<<mt, 256, SMEM32>>>(h1, 32, B11i, t, 896, N, 14);
    gather_kernel<64,false,false,false,false><<<(N + 3) / 4, 256>>>(
        t, 896, 0, 14, nbr, mask, nullptr, p64, 64, 0, nullptr, nullptr, N);

    tcmm_kernel<32><<<mt, 256, SMEM32>>>(h1, 32, B11i + (size_t)14 * 2 * 8 * 32, t, 832, N, 13);
    gather_kernel<64,false,true,true,true><<<(N + 3) / 4, 256>>>(
        t, 832, 14, 13, nbr, mask, b11, out, 128, 64, x, p64, N);
}

// round 11
// speedup vs baseline: 2.1338x; 1.0770x over previous
#include <cuda_runtime.h>
#include <cuda_bf16.h>
#include <cuda_fp16.h>
#include <cstdint>

// ---------------------------------------------------------------------------
// InceptionResNet sparse-conv block.
//   t = f @ concat_k(W_k)  via warp-level mma.sync bf16 (split-fp32:
//   hi*hi + hi*lo + lo*hi, fp32 accum)  [tcgen05 unavailable: harness PTX
//   targets compute_103 without the 'a' suffix]
//   conv3(f)[i] = sum_k mask[i,k] * t[nbr[i,k], k*Cout:(k+1)*Cout]
// R11: t scratch in fp16 (halves t write + gather-read traffic);
//      W11 conv single-pass (no p64 partial); launches reordered so the
//      ncu fixed slot captures tcmm<128>.
// ---------------------------------------------------------------------------

#define NPTS 500000

__device__ __half g_t[896000000];     // 1.792 GB fp16 scratch
                                      //  t_a = [0 .. N*896)      (W10 pass)
                                      //  t_b = [448M .. 448M+N*896) (W01 pass)
                                      //  whole = [0 .. N*1728)   (W11 pass)
__device__ float g_h0 [NPTS * 32];
__device__ float g_h1 [NPTS * 32];
__device__ float g_h0b[NPTS * 32];

// B fragment images: per tile, layout [s(k16)][f(n8)][lane][hi b0,b1, lo b0,b1]
__device__ uint4 g_B10i[14 * 8 * 8 * 32];   // W10: K=128 -> NS=8, 14 n-tiles
__device__ uint4 g_B01i[14 * 2 * 8 * 32];   // W01: K=32  -> NS=2, 14 n-tiles
__device__ uint4 g_B11i[27 * 2 * 8 * 32];   // W11: K=32  -> NS=2, 27 n-tiles

// ---------------------------------------------------------------------------
// helpers
// ---------------------------------------------------------------------------
__device__ __forceinline__ void splitf(float x, uint16_t& h, uint16_t& l) {
    __nv_bfloat16 hb = __float2bfloat16(x);
    __nv_bfloat16 lb = __float2bfloat16(x - __bfloat162float(hb));
    h = __bfloat16_as_ushort(hb);
    l = __bfloat16_as_ushort(lb);
}

__device__ __forceinline__ void mma16816(float* c, const uint32_t* a,
                                         uint32_t b0, uint32_t b1) {
    asm volatile(
        "mma.sync.aligned.m16n8k16.row.col.f32.bf16.bf16.f32 "
        "{%0,%1,%2,%3}, {%4,%5,%6,%7}, {%8,%9}, {%0,%1,%2,%3};"
        : "+f"(c[0]), "+f"(c[1]), "+f"(c[2]), "+f"(c[3])
        : "r"(a[0]), "r"(a[1]), "r"(a[2]), "r"(a[3]), "r"(b0), "r"(b1));
}

__device__ __forceinline__ void cp_async16(void* sdst, const void* gsrc) {
    uint32_t s;
    asm("{ .reg .u64 t; cvta.to.shared.u64 t, %1; cvt.u32.u64 %0, t; }"
        : "=r"(s) : "l"(sdst));
    asm volatile("cp.async.ca.shared.global [%0], [%1], 16;" :: "r"(s), "l"(gsrc));
}
__device__ __forceinline__ void cp_commit() {
    asm volatile("cp.async.commit_group;" ::: "memory");
}
__device__ __forceinline__ void cp_wait0() {
    asm volatile("cp.async.wait_group 0;" ::: "memory");
}

// ---------------------------------------------------------------------------
// Weight prep: B fragment images (unchanged).
// lane l (g=l>>2, t=l&3): b0={B[16s+2t][n],B[16s+2t+1][n]}, b1={..+8,..+9},
// n = j*64 + f*8 + g, B[k][n] = W[k27][k][c] (n = k27*Co + c).
// ---------------------------------------------------------------------------
template<int CIN, int CO>
__device__ __forceinline__ void prep_one(const float* __restrict__ W,
                                         uint4* __restrict__ img,
                                         int ntiles, int idx) {
    const int NS = CIN / 16;
    const int total = ntiles * NS * 8 * 32;
    if (idx >= total) return;
    int l = idx & 31, f = (idx >> 5) & 7, s = (idx >> 8) % NS, j = idx / (NS * 256);
    int g = l >> 2, t = l & 3;
    int n = j * 64 + f * 8 + g;
    int k27 = n / CO, c = n % CO;
    bool vn = (n < 27 * CO);
    uint16_t h[4], lo[4];
    int kb[4] = {16 * s + 2 * t, 16 * s + 2 * t + 1, 16 * s + 2 * t + 8, 16 * s + 2 * t + 9};
#pragma unroll
    for (int i = 0; i < 4; i++) {
        float v = vn ? W[((size_t)k27 * CIN + kb[i]) * CO + c] : 0.f;
        splitf(v, h[i], lo[i]);
    }
    uint4 r;
    r.x = ((uint32_t)h[1] << 16)  | h[0];
    r.y = ((uint32_t)h[3] << 16)  | h[2];
    r.z = ((uint32_t)lo[1] << 16) | lo[0];
    r.w = ((uint32_t)lo[3] << 16) | lo[2];
    img[idx] = r;
}

__global__ void prep_img(const float* __restrict__ W10,
                         const float* __restrict__ W01,
                         const float* __restrict__ W11)
{
    int idx = blockIdx.x * 256 + threadIdx.x;
    prep_one<128, 32>(W10, g_B10i, 14, idx);
    prep_one<32, 32>(W01, g_B01i, 14, idx);
    prep_one<32, 64>(W11, g_B11i, 27, idx);
}

// ---------------------------------------------------------------------------
// Tensor-core GEMM: C[M, ntiles*64] = A[M, KDIM] @ B (pre-imaged, split bf16)
// CTA = 256 threads (8 warps); warp w owns m16 block w. B double-buffered.
// Output stored as fp16 (half2 pairs).
// ---------------------------------------------------------------------------
template<int KDIM>
__global__ __launch_bounds__(256)
void tcmm_kernel(const float* __restrict__ A, int lda,
                 const uint4* __restrict__ Bimg,
                 __half* __restrict__ C, int ldc, int M, int ntiles)
{
    constexpr int NS = KDIM / 16;
    constexpr int ASZ4 = NS * 8 * 32 * 2;   // A image (uint4 units)
    constexpr int BSZ4 = NS * 8 * 32;       // one B buffer (uint4 units)

    extern __shared__ uint4 smem4[];
    uint4* Aimg = smem4;
    uint4* Bbuf0 = smem4 + ASZ4;
    uint4* Bbuf1 = smem4 + ASZ4 + BSZ4;
    uint32_t* Aimg32 = reinterpret_cast<uint32_t*>(Aimg);

    const int tid  = threadIdx.x;
    const int wid  = tid >> 5;
    const int lane = tid & 31;
    const int m0   = blockIdx.x * 128;

    // ---- stage A: 256 threads, each stages half a row ----
    {
        const int r = tid & 127;
        const int khalf = tid >> 7;
        constexpr int QPT = KDIM / 8;
        const bool vrow = (m0 + r) < M;
        const float* ap = A + (size_t)(m0 + r) * lda;
        const int mblk = r >> 4;
        const int half = (r >> 3) & 1;
        const int g    = r & 7;
#pragma unroll
        for (int qq = 0; qq < QPT; qq++) {
            int q = khalf * QPT + qq;
            float4 a = vrow ? *reinterpret_cast<const float4*>(ap + q * 4)
                            : make_float4(0.f, 0.f, 0.f, 0.f);
            uint16_t h0, l0, h1, l1, h2, l2, h3, l3;
            splitf(a.x, h0, l0); splitf(a.y, h1, l1);
            splitf(a.z, h2, l2); splitf(a.w, h3, l3);
            uint32_t hiA = ((uint32_t)h1 << 16) | h0, loA = ((uint32_t)l1 << 16) | l0;
            uint32_t hiB = ((uint32_t)h3 << 16) | h2, loB = ((uint32_t)l3 << 16) | l2;
            int k = q * 4;
            int s  = k >> 4;
            int pA = (k >> 1) & 7;
            int pB = pA + 1;
            int laneA = g * 4 + (pA & 3), slotA = half + ((pA >> 2) << 1);
            int laneB = g * 4 + (pB & 3), slotB = half + ((pB >> 2) << 1);
            uint32_t baseA = (((s * 8 + mblk) * 32 + laneA) * 2) * 4;
            uint32_t baseB = (((s * 8 + mblk) * 32 + laneB) * 2) * 4;
            Aimg32[baseA + slotA]     = hiA;
            Aimg32[baseA + 4 + slotA] = loA;
            Aimg32[baseB + slotB]     = hiB;
            Aimg32[baseB + 4 + slotB] = loB;
        }
    }

    // ---- prefetch B tile 0 ----
    {
        const uint4* src = Bimg;
#pragma unroll
        for (int i = 0; i < BSZ4 / 256; i++)
            cp_async16(&Bbuf0[tid + i * 256], &src[tid + i * 256]);
        cp_commit();
    }

    const int g = lane >> 2;
    const int t = lane & 3;

    for (int j = 0; j < ntiles; j++) {
        uint4* Bcur = (j & 1) ? Bbuf1 : Bbuf0;
        uint4* Bnxt = (j & 1) ? Bbuf0 : Bbuf1;

        cp_wait0();
        __syncthreads();

        if (j + 1 < ntiles) {
            const uint4* src = Bimg + (size_t)(j + 1) * BSZ4;
#pragma unroll
            for (int i = 0; i < BSZ4 / 256; i++)
                cp_async16(&Bnxt[tid + i * 256], &src[tid + i * 256]);
            cp_commit();
        } else {
            cp_commit();
        }

        float acc[8][4];
#pragma unroll
        for (int f = 0; f < 8; f++)
#pragma unroll
            for (int i = 0; i < 4; i++) acc[f][i] = 0.f;

#pragma unroll
        for (int s = 0; s < NS; s++) {
            int base = ((s * 8 + wid) * 32 + lane) * 2;
            uint4 ah = Aimg[base];
            uint4 al = Aimg[base + 1];
            const uint32_t* ahp = reinterpret_cast<const uint32_t*>(&ah);
            const uint32_t* alp = reinterpret_cast<const uint32_t*>(&al);
#pragma unroll
            for (int f = 0; f < 8; f++) {
                uint4 b = Bcur[(s * 8 + f) * 32 + lane];
                mma16816(acc[f], ahp, b.x, b.y);   // hi*hi
                mma16816(acc[f], ahp, b.z, b.w);   // hi*lo
                mma16816(acc[f], alp, b.x, b.y);   // lo*hi
            }
        }

        // ---- epilogue: warp's 16 rows x 64 cols, fp16 stores ----
        int mrow0 = m0 + wid * 16 + g;
#pragma unroll
        for (int f = 0; f < 8; f++) {
            int ncol = j * 64 + f * 8 + 2 * t;
            if (mrow0 < M)
                *reinterpret_cast<__half2*>(C + (size_t)mrow0 * ldc + ncol) =
                    __floats2half2_rn(acc[f][0], acc[f][1]);
            if (mrow0 + 8 < M)
                *reinterpret_cast<__half2*>(C + (size_t)(mrow0 + 8) * ldc + ncol) =
                    __floats2half2_rn(acc[f][2], acc[f][3]);
        }
    }
}

// ---------------------------------------------------------------------------
// fp32 SGEMM for the small 1x1 convs (W00, W02) — proven kernel.
// ---------------------------------------------------------------------------
template<bool BIAS, bool RELU, bool RES>
__global__ __launch_bounds__(128)
void sgemm_kernel(const float* __restrict__ A, int lda,
                  const float* __restrict__ B, int ldb,
                  float* __restrict__ C, int ldc,
                  int M, int K, int Ncol,
                  const float* __restrict__ bias,
                  const float* __restrict__ res, int ldres)
{
    __shared__ float As[16][128];
    __shared__ float Bs[16][64];

    const int tid = threadIdx.x;
    const int tx  = tid & 7;
    const int ty  = tid >> 3;
    const int m0  = blockIdx.x * 128;
    const int n0  = blockIdx.y * 64;

    float acc[8][8];
#pragma unroll
    for (int i = 0; i < 8; i++)
#pragma unroll
        for (int j = 0; j < 8; j++) acc[i][j] = 0.f;

    for (int k0 = 0; k0 < K; k0 += 16) {
#pragma unroll
        for (int i = 0; i < 4; i++) {
            int v  = tid + i * 128;
            int r  = v >> 2;
            int kk = (v & 3) * 4;
            int m  = m0 + r;
            float4 a = make_float4(0.f, 0.f, 0.f, 0.f);
            if (m < M)
                a = *reinterpret_cast<const float4*>(A + (size_t)m * lda + k0 + kk);
            As[kk + 0][r] = a.x; As[kk + 1][r] = a.y;
            As[kk + 2][r] = a.z; As[kk + 3][r] = a.w;
        }
#pragma unroll
        for (int i = 0; i < 2; i++) {
            int v  = tid + i * 128;
            int kk = v >> 4;
            int n4 = (v & 15) * 4;
            float4 b = make_float4(0.f, 0.f, 0.f, 0.f);
            if (n0 + n4 < Ncol)
                b = *reinterpret_cast<const float4*>(B + (size_t)(k0 + kk) * ldb + n0 + n4);
            *reinterpret_cast<float4*>(&Bs[kk][n4]) = b;
        }
        __syncthreads();

#pragma unroll
        for (int kk = 0; kk < 16; kk++) {
            float4 a0 = *reinterpret_cast<const float4*>(&As[kk][ty * 8]);
            float4 a1 = *reinterpret_cast<const float4*>(&As[kk][ty * 8 + 4]);
            float4 b0 = *reinterpret_cast<const float4*>(&Bs[kk][tx * 8]);
            float4 b1 = *reinterpret_cast<const float4*>(&Bs[kk][tx * 8 + 4]);
            float a[8] = {a0.x, a0.y, a0.z, a0.w, a1.x, a1.y, a1.z, a1.w};
            float b[8] = {b0.x, b0.y, b0.z, b0.w, b1.x, b1.y, b1.z, b1.w};
#pragma unroll
            for (int i = 0; i < 8; i++)
#pragma unroll
                for (int j = 0; j < 8; j++)
                    acc[i][j] = fmaf(a[i], b[j], acc[i][j]);
        }
        __syncthreads();
    }

#pragma unroll
    for (int i = 0; i < 8; i++) {
        int m = m0 + ty * 8 + i;
        if (m >= M) continue;
#pragma unroll
        for (int j = 0; j < 8; j++) {
            int n = n0 + tx * 8 + j;
            if (n >= Ncol) continue;
            float v = acc[i][j];
            if (BIAS) v += bias[n];
            if (RELU) v = fmaxf(v, 0.f);
            if (RES)  v += res[(size_t)m * ldres + n];
            C[(size_t)m * ldc + n] = v;
        }
    }
}

// ---------------------------------------------------------------------------
// Gather-sum over fp16 t: out[i,c] = sum_k mask[i,k] ? t[nbr[i,k], k*CO+c]
// FINAL adds bias (+relu) (+residual x slice); fp32 accumulation.
// ---------------------------------------------------------------------------
template<int CO, bool RELU, bool RES>
__global__ __launch_bounds__(256)
void gather_kernel(const __half* __restrict__ t, int ldt, int nk,
                   const int* __restrict__ nbr, const int* __restrict__ mask,
                   const float* __restrict__ bias,
                   float* __restrict__ out, int ldo, int ocol,
                   const float* __restrict__ res, int N)
{
    constexpr int PP = 256 / CO;
    __shared__ int s_nbr[PP * 27];
    __shared__ int s_msk[PP * 27];

    const int tid = threadIdx.x;
    const int p0  = blockIdx.x * PP;

    if (tid < PP * 27) {
        int pt = tid / 27, kk = tid % 27;
        int g = p0 + pt;
        s_nbr[tid] = (g < N) ? nbr[(size_t)g * 27 + kk] : 0;
        s_msk[tid] = (g < N) ? mask[(size_t)g * 27 + kk] : 0;
    }
    __syncthreads();

    const int p  = tid / CO;
    const int c  = tid % CO;
    const int gp = p0 + p;
    if (gp >= N) return;

    float acc = 0.f;
    for (int k = 0; k < nk; k++) {
        if (s_msk[p * 27 + k])
            acc += __half2float(t[(size_t)s_nbr[p * 27 + k] * ldt + k * CO + c]);
    }

    float v = acc + bias[c];
    if (RELU) v = fmaxf(v, 0.f);
    if (RES)  v += res[(size_t)gp * 128 + ocol + c];
    out[(size_t)gp * ldo + ocol + c] = v;
}

// ---------------------------------------------------------------------------
// Launch
// ---------------------------------------------------------------------------
extern "C" void kernel_launch(void* const* d_in, const int* in_sizes, int n_in,
                              void* d_out, int out_size)
{
    const float* x    = (const float*)d_in[0];
    const int*   nbr  = (const int*)  d_in[1];
    const int*   mask = (const int*)  d_in[2];
    const float* W00  = (const float*)d_in[3];
    const float* b00  = (const float*)d_in[4];
    const float* W01  = (const float*)d_in[5];
    const float* b01  = (const float*)d_in[6];
    const float* W02  = (const float*)d_in[7];
    const float* b02  = (const float*)d_in[8];
    const float* W10  = (const float*)d_in[9];
    const float* b10  = (const float*)d_in[10];
    const float* W11  = (const float*)d_in[11];
    const float* b11  = (const float*)d_in[12];
    float* out = (float*)d_out;

    const int N = in_sizes[0] / 128;

    __half* t;
    float *h0, *h1, *h0b;
    uint4 *B10i, *B01i, *B11i;
    cudaGetSymbolAddress((void**)&t,    g_t);
    cudaGetSymbolAddress((void**)&h0,   g_h0);
    cudaGetSymbolAddress((void**)&h1,   g_h1);
    cudaGetSymbolAddress((void**)&h0b,  g_h0b);
    cudaGetSymbolAddress((void**)&B10i, g_B10i);
    cudaGetSymbolAddress((void**)&B01i, g_B01i);
    cudaGetSymbolAddress((void**)&B11i, g_B11i);

    __half* t_a = t;               // [N, 896] W10 results
    __half* t_b = t + 448000000;   // [N, 896] W01 results

    const int SMEM128 = 8 * 8 * 32 * 32 + 2 * 8 * 8 * 32 * 16;  // 131072
    const int SMEM32  = 2 * 8 * 32 * 32 + 2 * 2 * 8 * 32 * 16;  // 32768
    cudaFuncSetAttribute(tcmm_kernel<128>, cudaFuncAttributeMaxDynamicSharedMemorySize, SMEM128);
    cudaFuncSetAttribute(tcmm_kernel<32>,  cudaFuncAttributeMaxDynamicSharedMemorySize, SMEM32);

    const int mt = (N + 127) / 128;

    // (0) weight prep
    prep_img<<<112, 256>>>(W10, W01, W11);

    // (1) h0 = relu(x @ W00 + b00)
    sgemm_kernel<true,true,false><<<dim3(mt, 1), 128>>>(
        x, 128, W00, 32, h0, 32, N, 128, 32, b00, nullptr, 0);

    // (2) t_b = h0 @ W01cat
    tcmm_kernel<32><<<mt, 256, SMEM32>>>(h0, 32, B01i, t_b, 896, N, 14);

    // (3) t_a = x @ W10cat   <-- ncu fixed-slot target
    tcmm_kernel<128><<<mt, 256, SMEM128>>>(x, 128, B10i, t_a, 896, N, 14);

    // (4) h1 = relu(gather(t_a) + b10)
    gather_kernel<32,true,false><<<(N + 7) / 8, 256>>>(
        t_a, 896, 27, nbr, mask, b10, h1, 32, 0, nullptr, N);

    // (5) h0b = relu(gather(t_b) + b01)
    gather_kernel<32,true,false><<<(N + 7) / 8, 256>>>(
        t_b, 896, 27, nbr, mask, b01, h0b, 32, 0, nullptr, N);

    // (6) out[:, 0:64] = h0b @ W02 + b02 + x[:, 0:64]
    sgemm_kernel<true,false,true><<<dim3(mt, 1), 128>>>(
        h0b, 32, W02, 64, out, 128, N, 32, 64, b02, x, 128);

    // (7) t = h1 @ W11cat  (full 27 tiles, single pass, ldc=1728)
    tcmm_kernel<32><<<mt, 256, SMEM32>>>(h1, 32, B11i, t, 1728, N, 27);

    // (8) out[:, 64:128] = gather(t) + b11 + x[:, 64:128]
    gather_kernel<64,false,true><<<(N + 3) / 4, 256>>>(
        t, 1728, 27, nbr, mask, b11, out, 128, 64, x, N);
}

// round 13
// speedup vs baseline: 2.3605x; 1.1062x over previous
#include <cuda_runtime.h>
#include <cuda_bf16.h>
#include <cuda_fp16.h>
#include <cstdint>

// ---------------------------------------------------------------------------
// InceptionResNet sparse-conv block.
//   t = f @ concat_k(W_k)  via warp-level mma.sync bf16 (split-fp32:
//   hi*hi + hi*lo + lo*hi, fp32 accum)  [tcgen05 unavailable: harness PTX
//   targets compute_103 without 'a' suffix]
//   conv3(f)[i] = sum_k mask[i,k] * t[nbr[i,k], k*Cout:(k+1)*Cout]
// R12: tcmm m-tile 256 with 2 m-blocks/warp (1.67x less LDS per MMA);
//      half2-vectorized gathers; gather<32> at the ncu capture slot.
// ---------------------------------------------------------------------------

#define NPTS 500000

__device__ __half g_t[896000000];     // 1.792 GB fp16 scratch
__device__ float g_h0 [NPTS * 32];
__device__ float g_h1 [NPTS * 32];
__device__ float g_h0b[NPTS * 32];

// B fragment images: per tile, layout [s(k16)][f(n8)][lane][hi b0,b1, lo b0,b1]
__device__ uint4 g_B10i[14 * 8 * 8 * 32];   // W10: K=128 -> NS=8, 14 n-tiles
__device__ uint4 g_B01i[14 * 2 * 8 * 32];   // W01: K=32  -> NS=2, 14 n-tiles
__device__ uint4 g_B11i[27 * 2 * 8 * 32];   // W11: K=32  -> NS=2, 27 n-tiles

// ---------------------------------------------------------------------------
// helpers
// ---------------------------------------------------------------------------
__device__ __forceinline__ void splitf(float x, uint16_t& h, uint16_t& l) {
    __nv_bfloat16 hb = __float2bfloat16(x);
    __nv_bfloat16 lb = __float2bfloat16(x - __bfloat162float(hb));
    h = __bfloat16_as_ushort(hb);
    l = __bfloat16_as_ushort(lb);
}

__device__ __forceinline__ void mma16816(float* c, const uint32_t* a,
                                         uint32_t b0, uint32_t b1) {
    asm volatile(
        "mma.sync.aligned.m16n8k16.row.col.f32.bf16.bf16.f32 "
        "{%0,%1,%2,%3}, {%4,%5,%6,%7}, {%8,%9}, {%0,%1,%2,%3};"
        : "+f"(c[0]), "+f"(c[1]), "+f"(c[2]), "+f"(c[3])
        : "r"(a[0]), "r"(a[1]), "r"(a[2]), "r"(a[3]), "r"(b0), "r"(b1));
}

__device__ __forceinline__ void cp_async16(void* sdst, const void* gsrc) {
    uint32_t s;
    asm("{ .reg .u64 t; cvta.to.shared.u64 t, %1; cvt.u32.u64 %0, t; }"
        : "=r"(s) : "l"(sdst));
    asm volatile("cp.async.ca.shared.global [%0], [%1], 16;" :: "r"(s), "l"(gsrc));
}
__device__ __forceinline__ void cp_commit() {
    asm volatile("cp.async.commit_group;" ::: "memory");
}
__device__ __forceinline__ void cp_wait0() {
    asm volatile("cp.async.wait_group 0;" ::: "memory");
}

// ---------------------------------------------------------------------------
// Weight prep: B fragment images (unchanged layout).
// ---------------------------------------------------------------------------
template<int CIN, int CO>
__device__ __forceinline__ void prep_one(const float* __restrict__ W,
                                         uint4* __restrict__ img,
                                         int ntiles, int idx) {
    const int NS = CIN / 16;
    const int total = ntiles * NS * 8 * 32;
    if (idx >= total) return;
    int l = idx & 31, f = (idx >> 5) & 7, s = (idx >> 8) % NS, j = idx / (NS * 256);
    int g = l >> 2, t = l & 3;
    int n = j * 64 + f * 8 + g;
    int k27 = n / CO, c = n % CO;
    bool vn = (n < 27 * CO);
    uint16_t h[4], lo[4];
    int kb[4] = {16 * s + 2 * t, 16 * s + 2 * t + 1, 16 * s + 2 * t + 8, 16 * s + 2 * t + 9};
#pragma unroll
    for (int i = 0; i < 4; i++) {
        float v = vn ? W[((size_t)k27 * CIN + kb[i]) * CO + c] : 0.f;
        splitf(v, h[i], lo[i]);
    }
    uint4 r;
    r.x = ((uint32_t)h[1] << 16)  | h[0];
    r.y = ((uint32_t)h[3] << 16)  | h[2];
    r.z = ((uint32_t)lo[1] << 16) | lo[0];
    r.w = ((uint32_t)lo[3] << 16) | lo[2];
    img[idx] = r;
}

__global__ void prep_img(const float* __restrict__ W10,
                         const float* __restrict__ W01,
                         const float* __restrict__ W11)
{
    int idx = blockIdx.x * 256 + threadIdx.x;
    prep_one<128, 32>(W10, g_B10i, 14, idx);
    prep_one<32, 32>(W01, g_B01i, 14, idx);
    prep_one<32, 64>(W11, g_B11i, 27, idx);
}

// ---------------------------------------------------------------------------
// Tensor-core GEMM: C[M, ntiles*64] = A[M, KDIM] @ B (pre-imaged, split bf16)
// CTA = 256 threads (8 warps); m-tile = 256 rows; warp w owns m16 blocks
// 2w and 2w+1.  B double-buffered via cp.async. fp16 output.
//
// smem A image: [s][mblk(16)][lane][4 hi u32][4 lo u32]
// smem B bufs : 2 x [s][f(8)][lane][uint4]
// ---------------------------------------------------------------------------
template<int KDIM>
__global__ __launch_bounds__(256)
void tcmm_kernel(const float* __restrict__ A, int lda,
                 const uint4* __restrict__ Bimg,
                 __half* __restrict__ C, int ldc, int M, int ntiles)
{
    constexpr int NS = KDIM / 16;
    constexpr int ASZ4 = NS * 16 * 32 * 2;  // A image (uint4 units)
    constexpr int BSZ4 = NS * 8 * 32;       // one B buffer (uint4 units)

    extern __shared__ uint4 smem4[];
    uint4* Aimg = smem4;
    uint4* Bbuf0 = smem4 + ASZ4;
    uint4* Bbuf1 = smem4 + ASZ4 + BSZ4;
    uint32_t* Aimg32 = reinterpret_cast<uint32_t*>(Aimg);

    const int tid  = threadIdx.x;
    const int wid  = tid >> 5;
    const int lane = tid & 31;
    const int m0   = blockIdx.x * 256;

    // ---- stage A: each thread stages one full row ----
    {
        const int r = tid;
        const bool vrow = (m0 + r) < M;
        const float* ap = A + (size_t)(m0 + r) * lda;
        const int mblk = r >> 4;          // 0..15
        const int half = (r >> 3) & 1;
        const int g    = r & 7;
#pragma unroll
        for (int q = 0; q < KDIM / 4; q++) {
            float4 a = vrow ? *reinterpret_cast<const float4*>(ap + q * 4)
                            : make_float4(0.f, 0.f, 0.f, 0.f);
            uint16_t h0, l0, h1, l1, h2, l2, h3, l3;
            splitf(a.x, h0, l0); splitf(a.y, h1, l1);
            splitf(a.z, h2, l2); splitf(a.w, h3, l3);
            uint32_t hiA = ((uint32_t)h1 << 16) | h0, loA = ((uint32_t)l1 << 16) | l0;
            uint32_t hiB = ((uint32_t)h3 << 16) | h2, loB = ((uint32_t)l3 << 16) | l2;
            int k = q * 4;
            int s  = k >> 4;
            int pA = (k >> 1) & 7;
            int pB = pA + 1;
            int laneA = g * 4 + (pA & 3), slotA = half + ((pA >> 2) << 1);
            int laneB = g * 4 + (pB & 3), slotB = half + ((pB >> 2) << 1);
            uint32_t baseA = (((s * 16 + mblk) * 32 + laneA) * 2) * 4;
            uint32_t baseB = (((s * 16 + mblk) * 32 + laneB) * 2) * 4;
            Aimg32[baseA + slotA]     = hiA;
            Aimg32[baseA + 4 + slotA] = loA;
            Aimg32[baseB + slotB]     = hiB;
            Aimg32[baseB + 4 + slotB] = loB;
        }
    }

    // ---- prefetch B tile 0 ----
    {
        const uint4* src = Bimg;
#pragma unroll
        for (int i = 0; i < BSZ4 / 256; i++)
            cp_async16(&Bbuf0[tid + i * 256], &src[tid + i * 256]);
        cp_commit();
    }

    const int g = lane >> 2;
    const int t = lane & 3;
    const int mb0 = 2 * wid;

    for (int j = 0; j < ntiles; j++) {
        uint4* Bcur = (j & 1) ? Bbuf1 : Bbuf0;
        uint4* Bnxt = (j & 1) ? Bbuf0 : Bbuf1;

        cp_wait0();
        __syncthreads();

        if (j + 1 < ntiles) {
            const uint4* src = Bimg + (size_t)(j + 1) * BSZ4;
#pragma unroll
            for (int i = 0; i < BSZ4 / 256; i++)
                cp_async16(&Bnxt[tid + i * 256], &src[tid + i * 256]);
            cp_commit();
        } else {
            cp_commit();
        }

        float acc[2][8][4];
#pragma unroll
        for (int mb = 0; mb < 2; mb++)
#pragma unroll
            for (int f = 0; f < 8; f++)
#pragma unroll
                for (int i = 0; i < 4; i++) acc[mb][f][i] = 0.f;

#pragma unroll
        for (int s = 0; s < NS; s++) {
            uint4 ah[2], al[2];
#pragma unroll
            for (int mb = 0; mb < 2; mb++) {
                int base = ((s * 16 + mb0 + mb) * 32 + lane) * 2;
                ah[mb] = Aimg[base];
                al[mb] = Aimg[base + 1];
            }
#pragma unroll
            for (int f = 0; f < 8; f++) {
                uint4 b = Bcur[(s * 8 + f) * 32 + lane];
#pragma unroll
                for (int mb = 0; mb < 2; mb++) {
                    const uint32_t* ahp = reinterpret_cast<const uint32_t*>(&ah[mb]);
                    const uint32_t* alp = reinterpret_cast<const uint32_t*>(&al[mb]);
                    mma16816(acc[mb][f], ahp, b.x, b.y);   // hi*hi
                    mma16816(acc[mb][f], ahp, b.z, b.w);   // hi*lo
                    mma16816(acc[mb][f], alp, b.x, b.y);   // lo*hi
                }
            }
        }

        // ---- epilogue: 2 m-blocks x 64 cols, fp16 stores ----
#pragma unroll
        for (int mb = 0; mb < 2; mb++) {
            int mrow0 = m0 + (mb0 + mb) * 16 + g;
#pragma unroll
            for (int f = 0; f < 8; f++) {
                int ncol = j * 64 + f * 8 + 2 * t;
                if (mrow0 < M)
                    *reinterpret_cast<__half2*>(C + (size_t)mrow0 * ldc + ncol) =
                        __floats2half2_rn(acc[mb][f][0], acc[mb][f][1]);
                if (mrow0 + 8 < M)
                    *reinterpret_cast<__half2*>(C + (size_t)(mrow0 + 8) * ldc + ncol) =
                        __floats2half2_rn(acc[mb][f][2], acc[mb][f][3]);
            }
        }
    }
}

// ---------------------------------------------------------------------------
// fp32 SGEMM for the small 1x1 convs (W00, W02) — proven kernel.
// ---------------------------------------------------------------------------
template<bool BIAS, bool RELU, bool RES>
__global__ __launch_bounds__(128)
void sgemm_kernel(const float* __restrict__ A, int lda,
                  const float* __restrict__ B, int ldb,
                  float* __restrict__ C, int ldc,
                  int M, int K, int Ncol,
                  const float* __restrict__ bias,
                  const float* __restrict__ res, int ldres)
{
    __shared__ float As[16][128];
    __shared__ float Bs[16][64];

    const int tid = threadIdx.x;
    const int tx  = tid & 7;
    const int ty  = tid >> 3;
    const int m0  = blockIdx.x * 128;
    const int n0  = blockIdx.y * 64;

    float acc[8][8];
#pragma unroll
    for (int i = 0; i < 8; i++)
#pragma unroll
        for (int j = 0; j < 8; j++) acc[i][j] = 0.f;

    for (int k0 = 0; k0 < K; k0 += 16) {
#pragma unroll
        for (int i = 0; i < 4; i++) {
            int v  = tid + i * 128;
            int r  = v >> 2;
            int kk = (v & 3) * 4;
            int m  = m0 + r;
            float4 a = make_float4(0.f, 0.f, 0.f, 0.f);
            if (m < M)
                a = *reinterpret_cast<const float4*>(A + (size_t)m * lda + k0 + kk);
            As[kk + 0][r] = a.x; As[kk + 1][r] = a.y;
            As[kk + 2][r] = a.z; As[kk + 3][r] = a.w;
        }
#pragma unroll
        for (int i = 0; i < 2; i++) {
            int v  = tid + i * 128;
            int kk = v >> 4;
            int n4 = (v & 15) * 4;
            float4 b = make_float4(0.f, 0.f, 0.f, 0.f);
            if (n0 + n4 < Ncol)
                b = *reinterpret_cast<const float4*>(B + (size_t)(k0 + kk) * ldb + n0 + n4);
            *reinterpret_cast<float4*>(&Bs[kk][n4]) = b;
        }
        __syncthreads();

#pragma unroll
        for (int kk = 0; kk < 16; kk++) {
            float4 a0 = *reinterpret_cast<const float4*>(&As[kk][ty * 8]);
            float4 a1 = *reinterpret_cast<const float4*>(&As[kk][ty * 8 + 4]);
            float4 b0 = *reinterpret_cast<const float4*>(&Bs[kk][tx * 8]);
            float4 b1 = *reinterpret_cast<const float4*>(&Bs[kk][tx * 8 + 4]);
            float a[8] = {a0.x, a0.y, a0.z, a0.w, a1.x, a1.y, a1.z, a1.w};
            float b[8] = {b0.x, b0.y, b0.z, b0.w, b1.x, b1.y, b1.z, b1.w};
#pragma unroll
            for (int i = 0; i < 8; i++)
#pragma unroll
                for (int j = 0; j < 8; j++)
                    acc[i][j] = fmaf(a[i], b[j], acc[i][j]);
        }
        __syncthreads();
    }

#pragma unroll
    for (int i = 0; i < 8; i++) {
        int m = m0 + ty * 8 + i;
        if (m >= M) continue;
#pragma unroll
        for (int j = 0; j < 8; j++) {
            int n = n0 + tx * 8 + j;
            if (n >= Ncol) continue;
            float v = acc[i][j];
            if (BIAS) v += bias[n];
            if (RELU) v = fmaxf(v, 0.f);
            if (RES)  v += res[(size_t)m * ldres + n];
            C[(size_t)m * ldc + n] = v;
        }
    }
}

// ---------------------------------------------------------------------------
// Gather-sum over fp16 t, half2-vectorized: each thread covers 2 channels.
//   out[i, ocol+2c2 .. +1] = sum_k mask[i,k] ? t[nbr[i,k], k*CO + 2c2 ..]
// fp32 accumulation; adds bias (+relu) (+residual).
// ---------------------------------------------------------------------------
template<int CO, bool RELU, bool RES>
__global__ __launch_bounds__(256)
void gather_kernel(const __half2* __restrict__ t2, int ldt2, int nk,
                   const int* __restrict__ nbr, const int* __restrict__ mask,
                   const float* __restrict__ bias,
                   float* __restrict__ out, int ldo, int ocol,
                   const float* __restrict__ res, int N)
{
    constexpr int CO2 = CO / 2;
    constexpr int PP  = 256 / CO2;
    __shared__ int s_nbr[PP * 27];
    __shared__ int s_msk[PP * 27];

    const int tid = threadIdx.x;
    const int p0  = blockIdx.x * PP;

    for (int i = tid; i < PP * 27; i += 256) {
        int pt = i / 27, kk = i % 27;
        int g = p0 + pt;
        s_nbr[i] = (g < N) ? nbr[(size_t)g * 27 + kk] : 0;
        s_msk[i] = (g < N) ? mask[(size_t)g * 27 + kk] : 0;
    }
    __syncthreads();

    const int p  = tid / CO2;
    const int c2 = tid % CO2;
    const int gp = p0 + p;
    if (gp >= N) return;

    float ax = 0.f, ay = 0.f;
    for (int k = 0; k < nk; k++) {
        if (s_msk[p * 27 + k]) {
            __half2 v = t2[(size_t)s_nbr[p * 27 + k] * ldt2 + k * CO2 + c2];
            float2 f = __half22float2(v);
            ax += f.x; ay += f.y;
        }
    }

    const int c = 2 * c2;
    float vx = ax + bias[c];
    float vy = ay + bias[c + 1];
    if (RELU) { vx = fmaxf(vx, 0.f); vy = fmaxf(vy, 0.f); }
    if (RES) {
        float2 r = *reinterpret_cast<const float2*>(res + (size_t)gp * 128 + ocol + c);
        vx += r.x; vy += r.y;
    }
    *reinterpret_cast<float2*>(out + (size_t)gp * ldo + ocol + c) = make_float2(vx, vy);
}

// ---------------------------------------------------------------------------
// Launch
// ---------------------------------------------------------------------------
extern "C" void kernel_launch(void* const* d_in, const int* in_sizes, int n_in,
                              void* d_out, int out_size)
{
    const float* x    = (const float*)d_in[0];
    const int*   nbr  = (const int*)  d_in[1];
    const int*   mask = (const int*)  d_in[2];
    const float* W00  = (const float*)d_in[3];
    const float* b00  = (const float*)d_in[4];
    const float* W01  = (const float*)d_in[5];
    const float* b01  = (const float*)d_in[6];
    const float* W02  = (const float*)d_in[7];
    const float* b02  = (const float*)d_in[8];
    const float* W10  = (const float*)d_in[9];
    const float* b10  = (const float*)d_in[10];
    const float* W11  = (const float*)d_in[11];
    const float* b11  = (const float*)d_in[12];
    float* out = (float*)d_out;

    const int N = in_sizes[0] / 128;

    __half* t;
    float *h0, *h1, *h0b;
    uint4 *B10i, *B01i, *B11i;
    cudaGetSymbolAddress((void**)&t,    g_t);
    cudaGetSymbolAddress((void**)&h0,   g_h0);
    cudaGetSymbolAddress((void**)&h1,   g_h1);
    cudaGetSymbolAddress((void**)&h0b,  g_h0b);
    cudaGetSymbolAddress((void**)&B10i, g_B10i);
    cudaGetSymbolAddress((void**)&B01i, g_B01i);
    cudaGetSymbolAddress((void**)&B11i, g_B11i);

    __half* t_a = t;               // [N, 896] W10 results
    __half* t_b = t + 448000000;   // [N, 896] W01 results

    // smem: A image NS*16*32*32B + 2 B buffers NS*8*32*16B each
    const int SMEM128 = 8 * 16 * 32 * 32 + 2 * 8 * 8 * 32 * 16;  // 196608
    const int SMEM32  = 2 * 16 * 32 * 32 + 2 * 2 * 8 * 32 * 16;  // 49152
    cudaFuncSetAttribute(tcmm_kernel<128>, cudaFuncAttributeMaxDynamicSharedMemorySize, SMEM128);
    cudaFuncSetAttribute(tcmm_kernel<32>,  cudaFuncAttributeMaxDynamicSharedMemorySize, SMEM32);

    const int mt = (N + 255) / 256;

    // (0) weight prep
    prep_img<<<112, 256>>>(W10, W01, W11);

    // (1) h0 = relu(x @ W00 + b00)
    sgemm_kernel<true,true,false><<<dim3((N + 127) / 128, 1), 128>>>(
        x, 128, W00, 32, h0, 32, N, 128, 32, b00, nullptr, 0);

    // (2) t_b = h0 @ W01cat
    tcmm_kernel<32><<<mt, 256, SMEM32>>>(h0, 32, B01i, t_b, 896, N, 14);

    // (3) h0b = relu(gather(t_b) + b01)   <-- ncu fixed-slot target
    gather_kernel<32,true,false><<<(N + 15) / 16, 256>>>(
        (const __half2*)t_b, 448, 27, nbr, mask, b01, h0b, 32, 0, nullptr, N);

    // (4) t_a = x @ W10cat
    tcmm_kernel<128><<<mt, 256, SMEM128>>>(x, 128, B10i, t_a, 896, N, 14);

    // (5) h1 = relu(gather(t_a) + b10)
    gather_kernel<32,true,false><<<(N + 15) / 16, 256>>>(
        (const __half2*)t_a, 448, 27, nbr, mask, b10, h1, 32, 0, nullptr, N);

    // (6) out[:, 0:64] = h0b @ W02 + b02 + x[:, 0:64]
    sgemm_kernel<true,false,true><<<dim3((N + 127) / 128, 1), 128>>>(
        h0b, 32, W02, 64, out, 128, N, 32, 64, b02, x, 128);

    // (7) t = h1 @ W11cat  (full 27 tiles, single pass, ldc=1728)
    tcmm_kernel<32><<<mt, 256, SMEM32>>>(h1, 32, B11i, t, 1728, N, 27);

    // (8) out[:, 64:128] = gather(t) + b11 + x[:, 64:128]
    gather_kernel<64,false,true><<<(N + 7) / 8, 256>>>(
        (const __half2*)t, 864, 27, nbr, mask, b11, out, 128, 64, x, N);
}

// round 16
// speedup vs baseline: 3.2042x; 1.3574x over previous
#include <cuda_runtime.h>
#include <cuda_fp16.h>
#include <cstdint>

// ---------------------------------------------------------------------------
// InceptionResNet sparse-conv block.
//   t = f @ concat_k(W_k)  via warp-level mma.sync fp16 (fp32 accumulate)
//   conv3(f)[i] = sum_k mask[i,k] * t[nbr[i,k], k*Cout:(k+1)*Cout]
// R14: plain fp16 MMA (3x fewer tensor FLOPs vs split-bf16; error budget
//      justified by the measured fp16-t rounding impact 1.8e-6 -> 8.3e-5).
//      A/B fragments halve; tcmm<32> smem 24KB -> 8 CTAs/SM.
// ---------------------------------------------------------------------------

#define NPTS 500000

__device__ __half g_t[896000000];     // 1.792 GB fp16 scratch
__device__ float g_h0 [NPTS * 32];
__device__ float g_h1 [NPTS * 32];
__device__ float g_h0b[NPTS * 32];

// B fragment images (fp16): per tile, [s(k16)][fp(4)][lane][uint4 =
//   {f=2fp: b0,b1, f=2fp+1: b0,b1}]
__device__ uint4 g_B10i[14 * 8 * 4 * 32];   // W10: K=128 -> NS=8, 14 n-tiles
__device__ uint4 g_B01i[14 * 2 * 4 * 32];   // W01: K=32  -> NS=2, 14 n-tiles
__device__ uint4 g_B11i[27 * 2 * 4 * 32];   // W11: K=32  -> NS=2, 27 n-tiles

// ---------------------------------------------------------------------------
// helpers
// ---------------------------------------------------------------------------
__device__ __forceinline__ uint32_t f2h2(float x, float y) {
    __half2 h = __floats2half2_rn(x, y);
    return reinterpret_cast<uint32_t&>(h);
}

__device__ __forceinline__ void mma16816(float* c, const uint32_t* a,
                                         uint32_t b0, uint32_t b1) {
    asm volatile(
        "mma.sync.aligned.m16n8k16.row.col.f32.f16.f16.f32 "
        "{%0,%1,%2,%3}, {%4,%5,%6,%7}, {%8,%9}, {%0,%1,%2,%3};"
        : "+f"(c[0]), "+f"(c[1]), "+f"(c[2]), "+f"(c[3])
        : "r"(a[0]), "r"(a[1]), "r"(a[2]), "r"(a[3]), "r"(b0), "r"(b1));
}

__device__ __forceinline__ void cp_async16(void* sdst, const void* gsrc) {
    uint32_t s;
    asm("{ .reg .u64 t; cvta.to.shared.u64 t, %1; cvt.u32.u64 %0, t; }"
        : "=r"(s) : "l"(sdst));
    asm volatile("cp.async.ca.shared.global [%0], [%1], 16;" :: "r"(s), "l"(gsrc));
}
__device__ __forceinline__ void cp_commit() {
    asm volatile("cp.async.commit_group;" ::: "memory");
}
__device__ __forceinline__ void cp_wait0() {
    asm volatile("cp.async.wait_group 0;" ::: "memory");
}

// ---------------------------------------------------------------------------
// Weight prep: fp16 B fragment images.
// For (j, s, fp, lane): lane l (g=l>>2, t=l&3); for fe in {0,1}:
//   f = 2*fp+fe, n = j*64 + f*8 + g, B[k][n] = W[k27][k][c] (n = k27*Co + c)
//   b0 = {B[16s+2t][n], B[16s+2t+1][n]}, b1 = {B[16s+2t+8][n], ..+9}
// ---------------------------------------------------------------------------
template<int CIN, int CO>
__device__ __forceinline__ void prep_one(const float* __restrict__ W,
                                         uint4* __restrict__ img,
                                         int ntiles, int idx) {
    const int NS = CIN / 16;
    const int total = ntiles * NS * 4 * 32;
    if (idx >= total) return;
    int l = idx & 31, fp = (idx >> 5) & 3, s = (idx >> 7) % NS, j = idx / (NS * 128);
    int g = l >> 2, t = l & 3;
    int kb[4] = {16 * s + 2 * t, 16 * s + 2 * t + 1, 16 * s + 2 * t + 8, 16 * s + 2 * t + 9};
    uint32_t r[4];
#pragma unroll
    for (int fe = 0; fe < 2; fe++) {
        int f = 2 * fp + fe;
        int n = j * 64 + f * 8 + g;
        int k27 = n / CO, c = n % CO;
        bool vn = (n < 27 * CO);
        float v[4];
#pragma unroll
        for (int i = 0; i < 4; i++)
            v[i] = vn ? W[((size_t)k27 * CIN + kb[i]) * CO + c] : 0.f;
        r[2 * fe + 0] = f2h2(v[0], v[1]);
        r[2 * fe + 1] = f2h2(v[2], v[3]);
    }
    img[idx] = make_uint4(r[0], r[1], r[2], r[3]);
}

__global__ void prep_img(const float* __restrict__ W10,
                         const float* __restrict__ W01,
                         const float* __restrict__ W11)
{
    int idx = blockIdx.x * 256 + threadIdx.x;
    prep_one<128, 32>(W10, g_B10i, 14, idx);
    prep_one<32, 32>(W01, g_B01i, 14, idx);
    prep_one<32, 64>(W11, g_B11i, 27, idx);
}

// ---------------------------------------------------------------------------
// Tensor-core GEMM (plain fp16): C[M, ntiles*64] = A[M, KDIM] @ B
// CTA = 256 threads (8 warps); m-tile = 256 rows; warp w owns m16 blocks
// 2w, 2w+1. B double-buffered via cp.async. fp16 output.
//
// smem A image: [s][mblk(16)][lane][uint4 (4 a-regs)]
// smem B bufs : 2 x [s][fp(4)][lane][uint4]
// ---------------------------------------------------------------------------
template<int KDIM>
__global__ __launch_bounds__(256)
void tcmm_kernel(const float* __restrict__ A, int lda,
                 const uint4* __restrict__ Bimg,
                 __half* __restrict__ C, int ldc, int M, int ntiles)
{
    constexpr int NS = KDIM / 16;
    constexpr int ASZ4 = NS * 16 * 32;      // A image (uint4 units)
    constexpr int BSZ4 = NS * 4 * 32;       // one B buffer (uint4 units)

    extern __shared__ uint4 smem4[];
    uint4* Aimg = smem4;
    uint4* Bbuf0 = smem4 + ASZ4;
    uint4* Bbuf1 = smem4 + ASZ4 + BSZ4;
    uint32_t* Aimg32 = reinterpret_cast<uint32_t*>(Aimg);

    const int tid  = threadIdx.x;
    const int wid  = tid >> 5;
    const int lane = tid & 31;
    const int m0   = blockIdx.x * 256;

    // ---- stage A: each thread stages one full row, fp16 fragments ----
    {
        const int r = tid;
        const bool vrow = (m0 + r) < M;
        const float* ap = A + (size_t)(m0 + r) * lda;
        const int mblk = r >> 4;          // 0..15
        const int half = (r >> 3) & 1;
        const int g    = r & 7;
#pragma unroll
        for (int q = 0; q < KDIM / 4; q++) {
            float4 a = vrow ? *reinterpret_cast<const float4*>(ap + q * 4)
                            : make_float4(0.f, 0.f, 0.f, 0.f);
            uint32_t p0 = f2h2(a.x, a.y);
            uint32_t p1 = f2h2(a.z, a.w);
            int k = q * 4;
            int s  = k >> 4;
            int pA = (k >> 1) & 7;
            int pB = pA + 1;
            int laneA = g * 4 + (pA & 3), slotA = half + ((pA >> 2) << 1);
            int laneB = g * 4 + (pB & 3), slotB = half + ((pB >> 2) << 1);
            Aimg32[((s * 16 + mblk) * 32 + laneA) * 4 + slotA] = p0;
            Aimg32[((s * 16 + mblk) * 32 + laneB) * 4 + slotB] = p1;
        }
    }

    // ---- prefetch B tile 0 ----
    {
        const uint4* src = Bimg;
#pragma unroll
        for (int i = 0; i < (BSZ4 + 255) / 256; i++) {
            int v = tid + i * 256;
            if (v < BSZ4) cp_async16(&Bbuf0[v], &src[v]);
        }
        cp_commit();
    }

    const int g = lane >> 2;
    const int t = lane & 3;
    const int mb0 = 2 * wid;

    for (int j = 0; j < ntiles; j++) {
        uint4* Bcur = (j & 1) ? Bbuf1 : Bbuf0;
        uint4* Bnxt = (j & 1) ? Bbuf0 : Bbuf1;

        cp_wait0();
        __syncthreads();

        if (j + 1 < ntiles) {
            const uint4* src = Bimg + (size_t)(j + 1) * BSZ4;
#pragma unroll
            for (int i = 0; i < (BSZ4 + 255) / 256; i++) {
                int v = tid + i * 256;
                if (v < BSZ4) cp_async16(&Bnxt[v], &src[v]);
            }
            cp_commit();
        } else {
            cp_commit();
        }

        float acc[2][8][4];
#pragma unroll
        for (int mb = 0; mb < 2; mb++)
#pragma unroll
            for (int f = 0; f < 8; f++)
#pragma unroll
                for (int i = 0; i < 4; i++) acc[mb][f][i] = 0.f;

#pragma unroll
        for (int s = 0; s < NS; s++) {
            uint4 ah[2];
#pragma unroll
            for (int mb = 0; mb < 2; mb++)
                ah[mb] = Aimg[(s * 16 + mb0 + mb) * 32 + lane];
#pragma unroll
            for (int fp = 0; fp < 4; fp++) {
                uint4 b = Bcur[(s * 4 + fp) * 32 + lane];
#pragma unroll
                for (int mb = 0; mb < 2; mb++) {
                    const uint32_t* ahp = reinterpret_cast<const uint32_t*>(&ah[mb]);
                    mma16816(acc[mb][2 * fp + 0], ahp, b.x, b.y);
                    mma16816(acc[mb][2 * fp + 1], ahp, b.z, b.w);
                }
            }
        }

        // ---- epilogue: 2 m-blocks x 64 cols, fp16 stores ----
#pragma unroll
        for (int mb = 0; mb < 2; mb++) {
            int mrow0 = m0 + (mb0 + mb) * 16 + g;
#pragma unroll
            for (int f = 0; f < 8; f++) {
                int ncol = j * 64 + f * 8 + 2 * t;
                if (mrow0 < M)
                    *reinterpret_cast<__half2*>(C + (size_t)mrow0 * ldc + ncol) =
                        __floats2half2_rn(acc[mb][f][0], acc[mb][f][1]);
                if (mrow0 + 8 < M)
                    *reinterpret_cast<__half2*>(C + (size_t)(mrow0 + 8) * ldc + ncol) =
                        __floats2half2_rn(acc[mb][f][2], acc[mb][f][3]);
            }
        }
    }
}

// ---------------------------------------------------------------------------
// fp32 SGEMM for the small 1x1 convs (W00, W02) — proven kernel.
// ---------------------------------------------------------------------------
template<bool BIAS, bool RELU, bool RES>
__global__ __launch_bounds__(128)
void sgemm_kernel(const float* __restrict__ A, int lda,
                  const float* __restrict__ B, int ldb,
                  float* __restrict__ C, int ldc,
                  int M, int K, int Ncol,
                  const float* __restrict__ bias,
                  const float* __restrict__ res, int ldres)
{
    __shared__ float As[16][128];
    __shared__ float Bs[16][64];

    const int tid = threadIdx.x;
    const int tx  = tid & 7;
    const int ty  = tid >> 3;
    const int m0  = blockIdx.x * 128;
    const int n0  = blockIdx.y * 64;

    float acc[8][8];
#pragma unroll
    for (int i = 0; i < 8; i++)
#pragma unroll
        for (int j = 0; j < 8; j++) acc[i][j] = 0.f;

    for (int k0 = 0; k0 < K; k0 += 16) {
#pragma unroll
        for (int i = 0; i < 4; i++) {
            int v  = tid + i * 128;
            int r  = v >> 2;
            int kk = (v & 3) * 4;
            int m  = m0 + r;
            float4 a = make_float4(0.f, 0.f, 0.f, 0.f);
            if (m < M)
                a = *reinterpret_cast<const float4*>(A + (size_t)m * lda + k0 + kk);
            As[kk + 0][r] = a.x; As[kk + 1][r] = a.y;
            As[kk + 2][r] = a.z; As[kk + 3][r] = a.w;
        }
#pragma unroll
        for (int i = 0; i < 2; i++) {
            int v  = tid + i * 128;
            int kk = v >> 4;
            int n4 = (v & 15) * 4;
            float4 b = make_float4(0.f, 0.f, 0.f, 0.f);
            if (n0 + n4 < Ncol)
                b = *reinterpret_cast<const float4*>(B + (size_t)(k0 + kk) * ldb + n0 + n4);
            *reinterpret_cast<float4*>(&Bs[kk][n4]) = b;
        }
        __syncthreads();

#pragma unroll
        for (int kk = 0; kk < 16; kk++) {
            float4 a0 = *reinterpret_cast<const float4*>(&As[kk][ty * 8]);
            float4 a1 = *reinterpret_cast<const float4*>(&As[kk][ty * 8 + 4]);
            float4 b0 = *reinterpret_cast<const float4*>(&Bs[kk][tx * 8]);
            float4 b1 = *reinterpret_cast<const float4*>(&Bs[kk][tx * 8 + 4]);
            float a[8] = {a0.x, a0.y, a0.z, a0.w, a1.x, a1.y, a1.z, a1.w};
            float b[8] = {b0.x, b0.y, b0.z, b0.w, b1.x, b1.y, b1.z, b1.w};
#pragma unroll
            for (int i = 0; i < 8; i++)
#pragma unroll
                for (int j = 0; j < 8; j++)
                    acc[i][j] = fmaf(a[i], b[j], acc[i][j]);
        }
        __syncthreads();
    }

#pragma unroll
    for (int i = 0; i < 8; i++) {
        int m = m0 + ty * 8 + i;
        if (m >= M) continue;
#pragma unroll
        for (int j = 0; j < 8; j++) {
            int n = n0 + tx * 8 + j;
            if (n >= Ncol) continue;
            float v = acc[i][j];
            if (BIAS) v += bias[n];
            if (RELU) v = fmaxf(v, 0.f);
            if (RES)  v += res[(size_t)m * ldres + n];
            C[(size_t)m * ldc + n] = v;
        }
    }
}

// ---------------------------------------------------------------------------
// Gather-sum over fp16 t, half2-vectorized (unchanged from R13).
// ---------------------------------------------------------------------------
template<int CO, bool RELU, bool RES>
__global__ __launch_bounds__(256)
void gather_kernel(const __half2* __restrict__ t2, int ldt2, int nk,
                   const int* __restrict__ nbr, const int* __restrict__ mask,
                   const float* __restrict__ bias,
                   float* __restrict__ out, int ldo, int ocol,
                   const float* __restrict__ res, int N)
{
    constexpr int CO2 = CO / 2;
    constexpr int PP  = 256 / CO2;
    __shared__ int s_nbr[PP * 27];
    __shared__ int s_msk[PP * 27];

    const int tid = threadIdx.x;
    const int p0  = blockIdx.x * PP;

    for (int i = tid; i < PP * 27; i += 256) {
        int pt = i / 27, kk = i % 27;
        int g = p0 + pt;
        s_nbr[i] = (g < N) ? nbr[(size_t)g * 27 + kk] : 0;
        s_msk[i] = (g < N) ? mask[(size_t)g * 27 + kk] : 0;
    }
    __syncthreads();

    const int p  = tid / CO2;
    const int c2 = tid % CO2;
    const int gp = p0 + p;
    if (gp >= N) return;

    float ax = 0.f, ay = 0.f;
    for (int k = 0; k < nk; k++) {
        if (s_msk[p * 27 + k]) {
            __half2 v = t2[(size_t)s_nbr[p * 27 + k] * ldt2 + k * CO2 + c2];
            float2 f = __half22float2(v);
            ax += f.x; ay += f.y;
        }
    }

    const int c = 2 * c2;
    float vx = ax + bias[c];
    float vy = ay + bias[c + 1];
    if (RELU) { vx = fmaxf(vx, 0.f); vy = fmaxf(vy, 0.f); }
    if (RES) {
        float2 r = *reinterpret_cast<const float2*>(res + (size_t)gp * 128 + ocol + c);
        vx += r.x; vy += r.y;
    }
    *reinterpret_cast<float2*>(out + (size_t)gp * ldo + ocol + c) = make_float2(vx, vy);
}

// ---------------------------------------------------------------------------
// Launch
// ---------------------------------------------------------------------------
extern "C" void kernel_launch(void* const* d_in, const int* in_sizes, int n_in,
                              void* d_out, int out_size)
{
    const float* x    = (const float*)d_in[0];
    const int*   nbr  = (const int*)  d_in[1];
    const int*   mask = (const int*)  d_in[2];
    const float* W00  = (const float*)d_in[3];
    const float* b00  = (const float*)d_in[4];
    const float* W01  = (const float*)d_in[5];
    const float* b01  = (const float*)d_in[6];
    const float* W02  = (const float*)d_in[7];
    const float* b02  = (const float*)d_in[8];
    const float* W10  = (const float*)d_in[9];
    const float* b10  = (const float*)d_in[10];
    const float* W11  = (const float*)d_in[11];
    const float* b11  = (const float*)d_in[12];
    float* out = (float*)d_out;

    const int N = in_sizes[0] / 128;

    __half* t;
    float *h0, *h1, *h0b;
    uint4 *B10i, *B01i, *B11i;
    cudaGetSymbolAddress((void**)&t,    g_t);
    cudaGetSymbolAddress((void**)&h0,   g_h0);
    cudaGetSymbolAddress((void**)&h1,   g_h1);
    cudaGetSymbolAddress((void**)&h0b,  g_h0b);
    cudaGetSymbolAddress((void**)&B10i, g_B10i);
    cudaGetSymbolAddress((void**)&B01i, g_B01i);
    cudaGetSymbolAddress((void**)&B11i, g_B11i);

    __half* t_a = t;               // [N, 896] W10 results
    __half* t_b = t + 448000000;   // [N, 896] W01 results

    // smem: A image NS*16*32*16B + 2 B buffers NS*4*32*16B each
    const int SMEM128 = 8 * 16 * 32 * 16 + 2 * 8 * 4 * 32 * 16;  // 98304
    const int SMEM32  = 2 * 16 * 32 * 16 + 2 * 2 * 4 * 32 * 16;  // 24576
    cudaFuncSetAttribute(tcmm_kernel<128>, cudaFuncAttributeMaxDynamicSharedMemorySize, SMEM128);
    cudaFuncSetAttribute(tcmm_kernel<32>,  cudaFuncAttributeMaxDynamicSharedMemorySize, SMEM32);

    const int mt = (N + 255) / 256;

    // (0) weight prep
    prep_img<<<112, 256>>>(W10, W01, W11);

    // (1) h0 = relu(x @ W00 + b00)
    sgemm_kernel<true,true,false><<<dim3((N + 127) / 128, 1), 128>>>(
        x, 128, W00, 32, h0, 32, N, 128, 32, b00, nullptr, 0);

    // (2) t_b = h0 @ W01cat
    tcmm_kernel<32><<<mt, 256, SMEM32>>>(h0, 32, B01i, t_b, 896, N, 14);

    // (3) t_a = x @ W10cat   <-- ncu fixed-slot target
    tcmm_kernel<128><<<mt, 256, SMEM128>>>(x, 128, B10i, t_a, 896, N, 14);

    // (4) h0b = relu(gather(t_b) + b01)
    gather_kernel<32,true,false><<<(N + 15) / 16, 256>>>(
        (const __half2*)t_b, 448, 27, nbr, mask, b01, h0b, 32, 0, nullptr, N);

    // (5) h1 = relu(gather(t_a) + b10)
    gather_kernel<32,true,false><<<(N + 15) / 16, 256>>>(
        (const __half2*)t_a, 448, 27, nbr, mask, b10, h1, 32, 0, nullptr, N);

    // (6) out[:, 0:64] = h0b @ W02 + b02 + x[:, 0:64]
    sgemm_kernel<true,false,true><<<dim3((N + 127) / 128, 1), 128>>>(
        h0b, 32, W02, 64, out, 128, N, 32, 64, b02, x, 128);

    // (7) t = h1 @ W11cat  (full 27 tiles, single pass, ldc=1728)
    tcmm_kernel<32><<<mt, 256, SMEM32>>>(h1, 32, B11i, t, 1728, N, 27);

    // (8) out[:, 64:128] = gather(t) + b11 + x[:, 64:128]
    gather_kernel<64,false,true><<<(N + 7) / 8, 256>>>(
        (const __half2*)t, 864, 27, nbr, mask, b11, out, 128, 64, x, N);
}